// round 7
// baseline (speedup 1.0000x reference)
#include <cuda_runtime.h>
#include <cuda_bf16.h>
#include <cstdint>

// Problem constants
#define CB 2
#define CT 2048
#define CD 1024
#define CNH 16
#define CHD 64
#define CM (CB*CT)              // 4096 rows

typedef __nv_bfloat16 bf16;

// ---------------------------------------------------------------------------
// Scratch (device globals)
// ---------------------------------------------------------------------------
__device__ bf16 g_ahi[CM*CD];           // hi/lo of GEMM A input (x, then att out)
__device__ bf16 g_alo[CM*CD];
__device__ bf16 g_whi[4*CD*CD];
__device__ bf16 g_wlo[4*CD*CD];
__device__ bf16 g_qhi[CM*CD];           // head-major [B,NH,T,64]
__device__ bf16 g_qlo[CM*CD];
__device__ bf16 g_khi[CM*CD];
__device__ bf16 g_klo[CM*CD];
__device__ bf16 g_vhi[CM*CD];
__device__ bf16 g_vlo[CM*CD];

// ---------------------------------------------------------------------------
// Common PTX helpers
// ---------------------------------------------------------------------------
static __device__ __forceinline__ void cp16(uint32_t d, const void* s) {
    asm volatile("cp.async.cg.shared.global [%0], [%1], 16;\n" :: "r"(d), "l"(s));
}
static __device__ __forceinline__ void cp_commit() {
    asm volatile("cp.async.commit_group;\n" ::: "memory");
}
template<int N> static __device__ __forceinline__ void cp_wait() {
    asm volatile("cp.async.wait_group %0;\n" :: "n"(N) : "memory");
}
static __device__ __forceinline__ void ldsm4(uint32_t& r0, uint32_t& r1,
                                             uint32_t& r2, uint32_t& r3, uint32_t a) {
    asm volatile("ldmatrix.sync.aligned.m8n8.x4.shared.b16 {%0,%1,%2,%3}, [%4];"
                 : "=r"(r0), "=r"(r1), "=r"(r2), "=r"(r3) : "r"(a));
}
static __device__ __forceinline__ void ldsm4t(uint32_t& r0, uint32_t& r1,
                                              uint32_t& r2, uint32_t& r3, uint32_t a) {
    asm volatile("ldmatrix.sync.aligned.m8n8.x4.trans.shared.b16 {%0,%1,%2,%3}, [%4];"
                 : "=r"(r0), "=r"(r1), "=r"(r2), "=r"(r3) : "r"(a));
}
static __device__ __forceinline__ void mma16816(float* c, const uint32_t* a,
                                                uint32_t b0, uint32_t b1) {
    asm volatile(
        "mma.sync.aligned.m16n8k16.row.col.f32.bf16.bf16.f32 "
        "{%0,%1,%2,%3}, {%4,%5,%6,%7}, {%8,%9}, {%0,%1,%2,%3};"
        : "+f"(c[0]), "+f"(c[1]), "+f"(c[2]), "+f"(c[3])
        : "r"(a[0]), "r"(a[1]), "r"(a[2]), "r"(a[3]), "r"(b0), "r"(b1));
}
static __device__ __forceinline__ uint32_t smem_u32(const void* p) {
    uint32_t r;
    asm("{ .reg .u64 t; cvta.to.shared.u64 t, %1; cvt.u32.u64 %0, t; }" : "=r"(r) : "l"(p));
    return r;
}

// ---------------------------------------------------------------------------
// fp32 -> bf16 hi/lo split (vectorized by 4)
// ---------------------------------------------------------------------------
__global__ __launch_bounds__(256)
void cvt_kernel(const float* __restrict__ s, bf16* __restrict__ hi,
                bf16* __restrict__ lo, int n4)
{
    int i = blockIdx.x * blockDim.x + threadIdx.x;
    if (i >= n4) return;
    float4 v = ((const float4*)s)[i];
    bf16 h0 = __float2bfloat16(v.x);
    bf16 h1 = __float2bfloat16(v.y);
    bf16 h2 = __float2bfloat16(v.z);
    bf16 h3 = __float2bfloat16(v.w);
    bf16 l0 = __float2bfloat16(v.x - __bfloat162float(h0));
    bf16 l1 = __float2bfloat16(v.y - __bfloat162float(h1));
    bf16 l2 = __float2bfloat16(v.z - __bfloat162float(h2));
    bf16 l3 = __float2bfloat16(v.w - __bfloat162float(h3));
    ((__nv_bfloat162*)hi)[2*i]   = __halves2bfloat162(h0, h1);
    ((__nv_bfloat162*)hi)[2*i+1] = __halves2bfloat162(h2, h3);
    ((__nv_bfloat162*)lo)[2*i]   = __halves2bfloat162(l0, l1);
    ((__nv_bfloat162*)lo)[2*i+1] = __halves2bfloat162(l2, l3);
}

// ---------------------------------------------------------------------------
// mma.sync bf16 GEMM with hi/lo 3-term fp32 emulation.
// mode 0: out = (C+bias)*scale as fp32 row-major [CM,CD] -> dst
// mode 1: out split hi/lo bf16, head-major [B,NH,T,64]   -> dhi,dlo
// 3 stages x 32KB = 96KB smem -> 2 CTAs/SM; one __syncthreads per k-tile.
// B fragments loaded per-n16-block to keep live regs < 128 (no spills).
// ---------------------------------------------------------------------------
#define GBM 128
#define GBN 128
#define GBK 32
#define GSTAGES 3
#define GNKT (CD/GBK)
#define PART_BYTES 8192
#define STG_BYTES (4*PART_BYTES)
#define GSMEM (GSTAGES*STG_BYTES)     // 96KB

static __device__ __forceinline__ uint32_t swz(int r, int c16) {
    return (uint32_t)(r * 64 + ((c16 ^ ((r >> 1) & 3)) << 4));
}

static __device__ __forceinline__ void g_load_stage(
    uint32_t sbase, int kt, int tid,
    const bf16* __restrict__ Ah, const bf16* __restrict__ Al,
    const bf16* __restrict__ Bh, const bf16* __restrict__ Bl,
    int bm, int bn)
{
    const int k0 = kt * GBK;
    const bf16* srcs[4] = { Ah, Al, Bh, Bl };
    #pragma unroll
    for (int p = 0; p < 4; p++) {
        const int rowbase = (p < 2) ? bm : bn;
        const bf16* src = srcs[p];
        #pragma unroll
        for (int i = 0; i < 2; i++) {
            const int id = tid + i * 256;
            const int r = id >> 2;
            const int c = id & 3;
            cp16(sbase + (uint32_t)p * PART_BYTES + swz(r, c),
                 src + (size_t)(rowbase + r) * CD + k0 + c * 8);
        }
    }
}

__global__ __launch_bounds__(256, 2)
void tc_gemm(const bf16* __restrict__ Ah, const bf16* __restrict__ Al,
             const bf16* __restrict__ Bh, const bf16* __restrict__ Bl,
             const float* __restrict__ bias, float* __restrict__ dst,
             bf16* __restrict__ dhi, bf16* __restrict__ dlo,
             float scale, int mode)
{
    extern __shared__ char dsm[];
    uint32_t sb = smem_u32(dsm);

    const int tid  = threadIdx.x;
    const int wid  = tid >> 5;
    const int lane = tid & 31;
    const int bm   = blockIdx.y * GBM;
    const int bn   = blockIdx.x * GBN;
    const int m0w  = (wid & 3) * 32;
    const int n0w  = (wid >> 2) * 64;

    float acc[2][8][4];
    #pragma unroll
    for (int i = 0; i < 2; i++)
        #pragma unroll
        for (int j = 0; j < 8; j++)
            #pragma unroll
            for (int k = 0; k < 4; k++) acc[i][j][k] = 0.f;

    // Preload stages 0,1
    #pragma unroll
    for (int s = 0; s < GSTAGES - 1; s++) {
        g_load_stage(sb + s * STG_BYTES, s, tid, Ah, Al, Bh, Bl, bm, bn);
        cp_commit();
    }

    const int lr = lane & 15;
    const int lc = lane >> 4;

    for (int kt = 0; kt < GNKT; kt++) {
        cp_wait<1>();              // stage kt complete (kt+1 may be in flight)
        __syncthreads();           // all warps done with stage (kt-1)%3

        // Prefetch stage kt+2 into buffer (kt+2)%3 == (kt-1)%3 (consumed last iter)
        if (kt + 2 < GNKT) {
            g_load_stage(sb + ((kt + 2) % GSTAGES) * STG_BYTES,
                         kt + 2, tid, Ah, Al, Bh, Bl, bm, bn);
        }
        cp_commit();

        const uint32_t stg = sb + (uint32_t)(kt % GSTAGES) * STG_BYTES;
        #pragma unroll
        for (int ks = 0; ks < 2; ks++) {
            const int c16 = 2 * ks + lc;
            uint32_t ah[2][4], al[2][4];
            #pragma unroll
            for (int mi = 0; mi < 2; mi++) {
                const int r = m0w + mi * 16 + lr;
                ldsm4(ah[mi][0], ah[mi][1], ah[mi][2], ah[mi][3],
                      stg + 0 * PART_BYTES + swz(r, c16));
                ldsm4(al[mi][0], al[mi][1], al[mi][2], al[mi][3],
                      stg + 1 * PART_BYTES + swz(r, c16));
            }
            // Per-n16-block B load + immediate consume (keeps live regs < 128)
            #pragma unroll
            for (int bj = 0; bj < 4; bj++) {
                const int r = n0w + bj * 16 + lr;
                uint32_t h0, h1, h2, h3, x0, x1, x2, x3;
                ldsm4(h0, h1, h2, h3, stg + 2 * PART_BYTES + swz(r, c16));
                ldsm4(x0, x1, x2, x3, stg + 3 * PART_BYTES + swz(r, c16));
                #pragma unroll
                for (int mi = 0; mi < 2; mi++) {
                    mma16816(acc[mi][bj*2],   ah[mi], h0, h2);
                    mma16816(acc[mi][bj*2],   ah[mi], x0, x2);
                    mma16816(acc[mi][bj*2],   al[mi], h0, h2);
                    mma16816(acc[mi][bj*2+1], ah[mi], h1, h3);
                    mma16816(acc[mi][bj*2+1], ah[mi], x1, x3);
                    mma16816(acc[mi][bj*2+1], al[mi], h1, h3);
                }
            }
        }
    }

    const int qr = lane >> 2;
    const int qc = (lane & 3) * 2;
    #pragma unroll
    for (int mi = 0; mi < 2; mi++) {
        #pragma unroll
        for (int nj = 0; nj < 8; nj++) {
            const int col = bn + n0w + nj * 8 + qc;
            const float b0 = __ldg(bias + col);
            const float b1 = __ldg(bias + col + 1);
            const int row0 = bm + m0w + mi * 16 + qr;
            float v00 = (acc[mi][nj][0] + b0) * scale;
            float v01 = (acc[mi][nj][1] + b1) * scale;
            float v10 = (acc[mi][nj][2] + b0) * scale;
            float v11 = (acc[mi][nj][3] + b1) * scale;
            if (mode == 0) {
                float2 a = make_float2(v00, v01);
                float2 b = make_float2(v10, v11);
                *(float2*)(dst + (size_t)row0 * CD + col)       = a;
                *(float2*)(dst + (size_t)(row0 + 8) * CD + col) = b;
            } else {
                const int h = col >> 6;
                const int d = col & 63;
                #pragma unroll
                for (int rr = 0; rr < 2; rr++) {
                    const int row = row0 + rr * 8;
                    const float x0 = rr ? v10 : v00;
                    const float x1 = rr ? v11 : v01;
                    const int bb = row >> 11;
                    const int t  = row & (CT - 1);
                    const size_t idx = ((size_t)((bb * CNH + h) * CT + t)) * 64 + d;
                    __nv_bfloat162 hh = __floats2bfloat162_rn(x0, x1);
                    __nv_bfloat162 ll = __floats2bfloat162_rn(
                        x0 - __low2float(hh), x1 - __high2float(hh));
                    *(__nv_bfloat162*)(dhi + idx) = hh;
                    *(__nv_bfloat162*)(dlo + idx) = ll;
                }
            }
        }
    }
}

// ---------------------------------------------------------------------------
// Tensor-core flash attention, ALiBi + causal, 3-term hi/lo for QK and PV.
// CTA: 64 q-rows (4 warps x m16), key tiles of 64, double-buffered KV stages.
// ---------------------------------------------------------------------------
#define A_QBYTES 16384
#define A_STG    32768
#define ASMEM    (A_QBYTES + 2*A_STG)

static __device__ __forceinline__ uint32_t swz128(int r, int c16) {
    return (uint32_t)(r * 128 + ((c16 ^ (r & 7)) << 4));
}

static __device__ __forceinline__ void a_load_kv(
    uint32_t stg, int tid,
    const bf16* __restrict__ kh, const bf16* __restrict__ kl,
    const bf16* __restrict__ vh, const bf16* __restrict__ vl, int j0)
{
    const bf16* arr[4] = { kh, kl, vh, vl };
    #pragma unroll
    for (int i = 0; i < 16; i++) {
        const int id = tid + i * 128;
        const int p = id >> 9;
        const int inner = id & 511;
        const int r = inner >> 3, c = inner & 7;
        cp16(stg + (uint32_t)p * 8192 + swz128(r, c),
             arr[p] + (size_t)(j0 + r) * 64 + c * 8);
    }
}

__global__ __launch_bounds__(128, 2)
void attn_mma(const bf16* __restrict__ qh_, const bf16* __restrict__ ql_,
              const bf16* __restrict__ kh_, const bf16* __restrict__ kl_,
              const bf16* __restrict__ vh_, const bf16* __restrict__ vl_,
              bf16* __restrict__ ohi, bf16* __restrict__ olo)
{
    extern __shared__ char dsm[];
    const uint32_t sb = smem_u32(dsm);
    const uint32_t sqh = sb, sql = sb + 8192;
    const uint32_t stg0 = sb + A_QBYTES, stg1 = stg0 + A_STG;

    const int tid  = threadIdx.x;
    const int lane = tid & 31;
    const int w    = tid >> 5;
    const int tq   = 31 - (int)blockIdx.x;     // longest CTAs first
    const int h    = blockIdx.y;
    const int b    = blockIdx.z;
    const int i0   = tq * 64;
    const int njt  = tq + 1;

    const size_t base = (size_t)(b * CNH + h) * CT * 64;
    const bf16* qh = qh_ + base; const bf16* ql = ql_ + base;
    const bf16* kh = kh_ + base; const bf16* kl = kl_ + base;
    const bf16* vh = vh_ + base; const bf16* vl = vl_ + base;

    const float slope = exp2f(-0.5f * (float)(h + 1));

    // Q tile load
    #pragma unroll
    for (int i = 0; i < 8; i++) {
        const int id = tid + i * 128;
        const int hl = id >> 9;
        const int inner = id & 511;
        const int r = inner >> 3, c = inner & 7;
        cp16((hl ? sql : sqh) + swz128(r, c),
             (hl ? ql : qh) + (size_t)(i0 + r) * 64 + c * 8);
    }
    cp_commit();
    a_load_kv(stg0, tid, kh, kl, vh, vl, 0);
    cp_commit();

    cp_wait<1>();          // Q ready
    __syncthreads();

    const int lr = lane & 15;
    const int lc = lane >> 4;
    uint32_t qfh[4][4], qfl[4][4];
    #pragma unroll
    for (int kk = 0; kk < 4; kk++) {
        const int r = w * 16 + lr;
        ldsm4(qfh[kk][0], qfh[kk][1], qfh[kk][2], qfh[kk][3], sqh + swz128(r, kk*2 + lc));
        ldsm4(qfl[kk][0], qfl[kk][1], qfl[kk][2], qfl[kk][3], sql + swz128(r, kk*2 + lc));
    }

    const int qr = lane >> 2;
    const int qc = (lane & 3) * 2;
    const int irow0 = i0 + w * 16 + qr;
    const int irow1 = irow0 + 8;

    float O[8][4];
    #pragma unroll
    for (int nj = 0; nj < 8; nj++)
        #pragma unroll
        for (int e = 0; e < 4; e++) O[nj][e] = 0.f;
    float m0 = -1e30f, m1 = -1e30f, l0 = 0.f, l1 = 0.f;

    for (int jt = 0; jt < njt; jt++) {
        if (jt + 1 < njt) {
            a_load_kv((jt & 1) ? stg0 : stg1, tid, kh, kl, vh, vl, (jt + 1) * 64);
            cp_commit();
            cp_wait<1>();
        } else {
            cp_wait<0>();
        }
        __syncthreads();

        const uint32_t stg = (jt & 1) ? stg1 : stg0;
        const uint32_t skh = stg, skl = stg + 8192, svh = stg + 16384, svl = stg + 24576;

        // ---- S = Q K^T (3-term) ----
        float S[8][4];
        #pragma unroll
        for (int nj = 0; nj < 8; nj++)
            #pragma unroll
            for (int e = 0; e < 4; e++) S[nj][e] = 0.f;

        #pragma unroll
        for (int kk = 0; kk < 4; kk++) {
            #pragma unroll
            for (int n16 = 0; n16 < 4; n16++) {
                const int r = n16 * 16 + lr;
                uint32_t h0, h1, h2, h3, x0, x1, x2, x3;
                ldsm4(h0, h1, h2, h3, skh + swz128(r, kk*2 + lc));
                ldsm4(x0, x1, x2, x3, skl + swz128(r, kk*2 + lc));
                mma16816(S[n16*2],   qfh[kk], h0, h2);
                mma16816(S[n16*2],   qfh[kk], x0, x2);
                mma16816(S[n16*2],   qfl[kk], h0, h2);
                mma16816(S[n16*2+1], qfh[kk], h1, h3);
                mma16816(S[n16*2+1], qfh[kk], x1, x3);
                mma16816(S[n16*2+1], qfl[kk], h1, h3);
            }
        }

        // ---- ALiBi + causal + online softmax ----
        const int jbase = jt * 64;
        const bool lastt = (jt == njt - 1);
        float tmax0 = -1e30f, tmax1 = -1e30f;
        #pragma unroll
        for (int nj = 0; nj < 8; nj++) {
            const int j0c = jbase + nj * 8 + qc;
            #pragma unroll
            for (int e = 0; e < 4; e++) {
                const int j = j0c + (e & 1);
                const int i = (e >> 1) ? irow1 : irow0;
                float s = S[nj][e] + slope * (float)(j - i);
                if (lastt && j > i) s = -1e30f;
                S[nj][e] = s;
            }
            tmax0 = fmaxf(tmax0, fmaxf(S[nj][0], S[nj][1]));
            tmax1 = fmaxf(tmax1, fmaxf(S[nj][2], S[nj][3]));
        }
        tmax0 = fmaxf(tmax0, __shfl_xor_sync(0xFFFFFFFFu, tmax0, 1));
        tmax0 = fmaxf(tmax0, __shfl_xor_sync(0xFFFFFFFFu, tmax0, 2));
        tmax1 = fmaxf(tmax1, __shfl_xor_sync(0xFFFFFFFFu, tmax1, 1));
        tmax1 = fmaxf(tmax1, __shfl_xor_sync(0xFFFFFFFFu, tmax1, 2));

        const float mn0 = fmaxf(m0, tmax0);
        const float mn1 = fmaxf(m1, tmax1);
        const float cr0 = __expf(m0 - mn0);
        const float cr1 = __expf(m1 - mn1);
        m0 = mn0; m1 = mn1;

        float ls0 = 0.f, ls1 = 0.f;
        #pragma unroll
        for (int nj = 0; nj < 8; nj++) {
            S[nj][0] = __expf(S[nj][0] - mn0);
            S[nj][1] = __expf(S[nj][1] - mn0);
            S[nj][2] = __expf(S[nj][2] - mn1);
            S[nj][3] = __expf(S[nj][3] - mn1);
            ls0 += S[nj][0] + S[nj][1];
            ls1 += S[nj][2] + S[nj][3];
        }
        l0 = l0 * cr0 + ls0;
        l1 = l1 * cr1 + ls1;
        #pragma unroll
        for (int nj = 0; nj < 8; nj++) {
            O[nj][0] *= cr0; O[nj][1] *= cr0;
            O[nj][2] *= cr1; O[nj][3] *= cr1;
        }

        // ---- O += P V (3-term) ----
        #pragma unroll
        for (int kk = 0; kk < 4; kk++) {
            uint32_t ph[4], pl[4];
            {
                const float* sA = S[2*kk];
                const float* sB = S[2*kk + 1];
                __nv_bfloat162 h2, l2;
                h2 = __floats2bfloat162_rn(sA[0], sA[1]);
                l2 = __floats2bfloat162_rn(sA[0] - __low2float(h2), sA[1] - __high2float(h2));
                ph[0] = *(uint32_t*)&h2; pl[0] = *(uint32_t*)&l2;
                h2 = __floats2bfloat162_rn(sA[2], sA[3]);
                l2 = __floats2bfloat162_rn(sA[2] - __low2float(h2), sA[3] - __high2float(h2));
                ph[1] = *(uint32_t*)&h2; pl[1] = *(uint32_t*)&l2;
                h2 = __floats2bfloat162_rn(sB[0], sB[1]);
                l2 = __floats2bfloat162_rn(sB[0] - __low2float(h2), sB[1] - __high2float(h2));
                ph[2] = *(uint32_t*)&h2; pl[2] = *(uint32_t*)&l2;
                h2 = __floats2bfloat162_rn(sB[2], sB[3]);
                l2 = __floats2bfloat162_rn(sB[2] - __low2float(h2), sB[3] - __high2float(h2));
                ph[3] = *(uint32_t*)&h2; pl[3] = *(uint32_t*)&l2;
            }
            #pragma unroll
            for (int n16 = 0; n16 < 4; n16++) {
                const int r = kk * 16 + lr;
                uint32_t h0, h1, h2r, h3, x0, x1, x2, x3;
                ldsm4t(h0, h1, h2r, h3, svh + swz128(r, n16*2 + lc));
                ldsm4t(x0, x1, x2, x3, svl + swz128(r, n16*2 + lc));
                mma16816(O[n16*2],   ph, h0, h1);
                mma16816(O[n16*2],   ph, x0, x1);
                mma16816(O[n16*2],   pl, h0, h1);
                mma16816(O[n16*2+1], ph, h2r, h3);
                mma16816(O[n16*2+1], ph, x2, x3);
                mma16816(O[n16*2+1], pl, h2r, h3);
            }
        }
        __syncthreads();
    }

    // ---- normalize + hi/lo store ----
    l0 += __shfl_xor_sync(0xFFFFFFFFu, l0, 1);
    l0 += __shfl_xor_sync(0xFFFFFFFFu, l0, 2);
    l1 += __shfl_xor_sync(0xFFFFFFFFu, l1, 1);
    l1 += __shfl_xor_sync(0xFFFFFFFFu, l1, 2);
    const float inv0 = 1.0f / l0;
    const float inv1 = 1.0f / l1;

    #pragma unroll
    for (int nj = 0; nj < 8; nj++) {
        const int col = h * 64 + nj * 8 + qc;
        const size_t idx0 = (size_t)(b * CT + irow0) * CD + col;
        const size_t idx1 = (size_t)(b * CT + irow1) * CD + col;
        float o00 = O[nj][0] * inv0, o01 = O[nj][1] * inv0;
        float o10 = O[nj][2] * inv1, o11 = O[nj][3] * inv1;
        __nv_bfloat162 h2, l2;
        h2 = __floats2bfloat162_rn(o00, o01);
        l2 = __floats2bfloat162_rn(o00 - __low2float(h2), o01 - __high2float(h2));
        *(__nv_bfloat162*)(ohi + idx0) = h2;
        *(__nv_bfloat162*)(olo + idx0) = l2;
        h2 = __floats2bfloat162_rn(o10, o11);
        l2 = __floats2bfloat162_rn(o10 - __low2float(h2), o11 - __high2float(h2));
        *(__nv_bfloat162*)(ohi + idx1) = h2;
        *(__nv_bfloat162*)(olo + idx1) = l2;
    }
}

// ---------------------------------------------------------------------------
extern "C" void kernel_launch(void* const* d_in, const int* in_sizes, int n_in,
                              void* d_out, int out_size)
{
    (void)in_sizes; (void)n_in; (void)out_size;
    const float* x  = (const float*)d_in[0];
    const float* Wq = (const float*)d_in[1];
    const float* bq = (const float*)d_in[2];
    const float* Wk = (const float*)d_in[3];
    const float* bk = (const float*)d_in[4];
    const float* Wv = (const float*)d_in[5];
    const float* bv = (const float*)d_in[6];
    const float* Wp = (const float*)d_in[7];
    const float* bp = (const float*)d_in[8];

    bf16 *ahi, *alo, *whi, *wlo, *qhi, *qlo, *khi, *klo, *vhi, *vlo;
    cudaGetSymbolAddress((void**)&ahi, g_ahi);
    cudaGetSymbolAddress((void**)&alo, g_alo);
    cudaGetSymbolAddress((void**)&whi, g_whi);
    cudaGetSymbolAddress((void**)&wlo, g_wlo);
    cudaGetSymbolAddress((void**)&qhi, g_qhi);
    cudaGetSymbolAddress((void**)&qlo, g_qlo);
    cudaGetSymbolAddress((void**)&khi, g_khi);
    cudaGetSymbolAddress((void**)&klo, g_klo);
    cudaGetSymbolAddress((void**)&vhi, g_vhi);
    cudaGetSymbolAddress((void**)&vlo, g_vlo);

    cudaFuncSetAttribute(tc_gemm,  cudaFuncAttributeMaxDynamicSharedMemorySize, GSMEM);
    cudaFuncSetAttribute(attn_mma, cudaFuncAttributeMaxDynamicSharedMemorySize, ASMEM);

    const int WN = CD * CD;
    const float invs = 0.17677669529663687f;   // 1024^(-0.25)

    cvt_kernel<<<(CM*CD/4 + 255)/256, 256>>>(x,  ahi, alo, CM*CD/4);
    cvt_kernel<<<(WN/4 + 255)/256, 256>>>(Wq, whi + 0*WN, wlo + 0*WN, WN/4);
    cvt_kernel<<<(WN/4 + 255)/256, 256>>>(Wk, whi + 1*WN, wlo + 1*WN, WN/4);
    cvt_kernel<<<(WN/4 + 255)/256, 256>>>(Wv, whi + 2*WN, wlo + 2*WN, WN/4);
    cvt_kernel<<<(WN/4 + 255)/256, 256>>>(Wp, whi + 3*WN, wlo + 3*WN, WN/4);

    const dim3 gg(CD / GBN, CM / GBM);   // (8, 32)
    tc_gemm<<<gg, 256, GSMEM>>>(ahi, alo, whi + 0*WN, wlo + 0*WN, bq,
                                nullptr, qhi, qlo, invs, 1);
    tc_gemm<<<gg, 256, GSMEM>>>(ahi, alo, whi + 1*WN, wlo + 1*WN, bk,
                                nullptr, khi, klo, invs, 1);
    tc_gemm<<<gg, 256, GSMEM>>>(ahi, alo, whi + 2*WN, wlo + 2*WN, bv,
                                nullptr, vhi, vlo, 1.0f, 1);

    attn_mma<<<dim3(32, CNH, CB), 128, ASMEM>>>(qhi, qlo, khi, klo, vhi, vlo, ahi, alo);

    tc_gemm<<<gg, 256, GSMEM>>>(ahi, alo, whi + 3*WN, wlo + 3*WN, bp,
                                (float*)d_out, nullptr, nullptr, 1.0f, 0);
}

// round 8
// speedup vs baseline: 1.3663x; 1.3663x over previous
#include <cuda_runtime.h>
#include <cuda_fp16.h>
#include <cstdint>

// Problem constants
#define CB 2
#define CT 2048
#define CD 1024
#define CNH 16
#define CHD 64
#define CM (CB*CT)              // 4096 rows

// ---------------------------------------------------------------------------
// Scratch (device globals)
// ---------------------------------------------------------------------------
__device__ __half g_ahi[CM*CD];         // A operand hi/lo (x, then att out)
__device__ __half g_alo[CM*CD];
__device__ __half g_wh[4*CD*CD];        // weights, single fp16
__device__ __half g_qh[CM*CD];          // Q hi/lo, head-major [B,NH,T,64]
__device__ __half g_ql[CM*CD];
__device__ __half g_kh[CM*CD];          // K single, head-major
__device__ __half g_vh[CM*CD];          // V single, head-major

// ---------------------------------------------------------------------------
// PTX helpers
// ---------------------------------------------------------------------------
static __device__ __forceinline__ void cp16(uint32_t d, const void* s) {
    asm volatile("cp.async.cg.shared.global [%0], [%1], 16;\n" :: "r"(d), "l"(s));
}
static __device__ __forceinline__ void cp_commit() {
    asm volatile("cp.async.commit_group;\n" ::: "memory");
}
template<int N> static __device__ __forceinline__ void cp_wait() {
    asm volatile("cp.async.wait_group %0;\n" :: "n"(N) : "memory");
}
static __device__ __forceinline__ void ldsm4(uint32_t& r0, uint32_t& r1,
                                             uint32_t& r2, uint32_t& r3, uint32_t a) {
    asm volatile("ldmatrix.sync.aligned.m8n8.x4.shared.b16 {%0,%1,%2,%3}, [%4];"
                 : "=r"(r0), "=r"(r1), "=r"(r2), "=r"(r3) : "r"(a));
}
static __device__ __forceinline__ void ldsm4t(uint32_t& r0, uint32_t& r1,
                                              uint32_t& r2, uint32_t& r3, uint32_t a) {
    asm volatile("ldmatrix.sync.aligned.m8n8.x4.trans.shared.b16 {%0,%1,%2,%3}, [%4];"
                 : "=r"(r0), "=r"(r1), "=r"(r2), "=r"(r3) : "r"(a));
}
static __device__ __forceinline__ void mma16816(float* c, const uint32_t* a,
                                                uint32_t b0, uint32_t b1) {
    asm volatile(
        "mma.sync.aligned.m16n8k16.row.col.f32.f16.f16.f32 "
        "{%0,%1,%2,%3}, {%4,%5,%6,%7}, {%8,%9}, {%0,%1,%2,%3};"
        : "+f"(c[0]), "+f"(c[1]), "+f"(c[2]), "+f"(c[3])
        : "r"(a[0]), "r"(a[1]), "r"(a[2]), "r"(a[3]), "r"(b0), "r"(b1));
}
static __device__ __forceinline__ uint32_t smem_u32(const void* p) {
    uint32_t r;
    asm("{ .reg .u64 t; cvta.to.shared.u64 t, %1; cvt.u32.u64 %0, t; }" : "=r"(r) : "l"(p));
    return r;
}

// ---------------------------------------------------------------------------
// fp32 -> fp16 hi/lo split (A operand)
// ---------------------------------------------------------------------------
__global__ __launch_bounds__(256)
void cvt_split(const float* __restrict__ s, __half* __restrict__ hi,
               __half* __restrict__ lo, int n4)
{
    int i = blockIdx.x * blockDim.x + threadIdx.x;
    if (i >= n4) return;
    float4 v = ((const float4*)s)[i];
    __half2 h01 = __floats2half2_rn(v.x, v.y);
    __half2 h23 = __floats2half2_rn(v.z, v.w);
    __half2 l01 = __floats2half2_rn(v.x - __low2float(h01), v.y - __high2float(h01));
    __half2 l23 = __floats2half2_rn(v.z - __low2float(h23), v.w - __high2float(h23));
    ((__half2*)hi)[2*i]   = h01;
    ((__half2*)hi)[2*i+1] = h23;
    ((__half2*)lo)[2*i]   = l01;
    ((__half2*)lo)[2*i+1] = l23;
}

// fp32 -> fp16 single (B operand / weights)
__global__ __launch_bounds__(256)
void cvt_single(const float* __restrict__ s, __half* __restrict__ d, int n4)
{
    int i = blockIdx.x * blockDim.x + threadIdx.x;
    if (i >= n4) return;
    float4 v = ((const float4*)s)[i];
    ((__half2*)d)[2*i]   = __floats2half2_rn(v.x, v.y);
    ((__half2*)d)[2*i+1] = __floats2half2_rn(v.z, v.w);
}

// ---------------------------------------------------------------------------
// mma.sync fp16 GEMM, 2-term emulation: C = (Ah+Al) @ fp16(B)^T
// mode 0: out fp32 row-major [CM,CD];  mode 1: split fp16 head-major;
// mode 2: single fp16 head-major.
// Stage = Ahi|Alo|Bh = 24KB; 3 stages = 72KB -> 2 CTAs/SM.
// ---------------------------------------------------------------------------
#define GBM 128
#define GBN 128
#define GBK 32
#define GSTAGES 3
#define GNKT (CD/GBK)
#define PART_BYTES 8192
#define STG_BYTES (3*PART_BYTES)       // 24KB
#define GSMEM (GSTAGES*STG_BYTES)      // 72KB

static __device__ __forceinline__ uint32_t swz(int r, int c16) {
    return (uint32_t)(r * 64 + ((c16 ^ ((r >> 1) & 3)) << 4));
}

static __device__ __forceinline__ void g_load_stage(
    uint32_t sbase, int kt, int tid,
    const __half* __restrict__ Ah, const __half* __restrict__ Al,
    const __half* __restrict__ Bh, int bm, int bn)
{
    const int k0 = kt * GBK;
    const __half* srcs[3] = { Ah, Al, Bh };
    #pragma unroll
    for (int i = 0; i < 6; i++) {
        const int id = tid + i * 256;          // 0..1535
        const int p = id / 512;
        const int inner = id & 511;
        const int r = inner >> 2;
        const int c = inner & 3;
        const int rowbase = (p < 2) ? bm : bn;
        cp16(sbase + (uint32_t)p * PART_BYTES + swz(r, c),
             srcs[p] + (size_t)(rowbase + r) * CD + k0 + c * 8);
    }
}

__global__ __launch_bounds__(256, 2)
void tc_gemm(const __half* __restrict__ Ah, const __half* __restrict__ Al,
             const __half* __restrict__ Bh,
             const float* __restrict__ bias, float* __restrict__ dst,
             __half* __restrict__ dhi, __half* __restrict__ dlo,
             float scale, int mode)
{
    extern __shared__ char dsm[];
    uint32_t sb = smem_u32(dsm);

    const int tid  = threadIdx.x;
    const int wid  = tid >> 5;
    const int lane = tid & 31;
    const int bm   = blockIdx.y * GBM;
    const int bn   = blockIdx.x * GBN;
    const int m0w  = (wid & 3) * 32;
    const int n0w  = (wid >> 2) * 64;

    float acc[2][8][4];
    #pragma unroll
    for (int i = 0; i < 2; i++)
        #pragma unroll
        for (int j = 0; j < 8; j++)
            #pragma unroll
            for (int k = 0; k < 4; k++) acc[i][j][k] = 0.f;

    #pragma unroll
    for (int s = 0; s < GSTAGES - 1; s++) {
        g_load_stage(sb + s * STG_BYTES, s, tid, Ah, Al, Bh, bm, bn);
        cp_commit();
    }

    const int lr = lane & 15;
    const int lc = lane >> 4;

    for (int kt = 0; kt < GNKT; kt++) {
        cp_wait<1>();
        __syncthreads();

        if (kt + 2 < GNKT) {
            g_load_stage(sb + ((kt + 2) % GSTAGES) * STG_BYTES,
                         kt + 2, tid, Ah, Al, Bh, bm, bn);
        }
        cp_commit();

        const uint32_t stg = sb + (uint32_t)(kt % GSTAGES) * STG_BYTES;
        #pragma unroll
        for (int ks = 0; ks < 2; ks++) {
            const int c16 = 2 * ks + lc;
            uint32_t ah[2][4], al[2][4];
            #pragma unroll
            for (int mi = 0; mi < 2; mi++) {
                const int r = m0w + mi * 16 + lr;
                ldsm4(ah[mi][0], ah[mi][1], ah[mi][2], ah[mi][3],
                      stg + 0 * PART_BYTES + swz(r, c16));
                ldsm4(al[mi][0], al[mi][1], al[mi][2], al[mi][3],
                      stg + 1 * PART_BYTES + swz(r, c16));
            }
            #pragma unroll
            for (int bj = 0; bj < 4; bj++) {
                const int r = n0w + bj * 16 + lr;
                uint32_t h0, h1, h2, h3;
                ldsm4(h0, h1, h2, h3, stg + 2 * PART_BYTES + swz(r, c16));
                #pragma unroll
                for (int mi = 0; mi < 2; mi++) {
                    mma16816(acc[mi][bj*2],   ah[mi], h0, h2);
                    mma16816(acc[mi][bj*2],   al[mi], h0, h2);
                    mma16816(acc[mi][bj*2+1], ah[mi], h1, h3);
                    mma16816(acc[mi][bj*2+1], al[mi], h1, h3);
                }
            }
        }
    }

    const int qr = lane >> 2;
    const int qc = (lane & 3) * 2;
    #pragma unroll
    for (int mi = 0; mi < 2; mi++) {
        #pragma unroll
        for (int nj = 0; nj < 8; nj++) {
            const int col = bn + n0w + nj * 8 + qc;
            const float b0 = __ldg(bias + col);
            const float b1 = __ldg(bias + col + 1);
            const int row0 = bm + m0w + mi * 16 + qr;
            float v00 = (acc[mi][nj][0] + b0) * scale;
            float v01 = (acc[mi][nj][1] + b1) * scale;
            float v10 = (acc[mi][nj][2] + b0) * scale;
            float v11 = (acc[mi][nj][3] + b1) * scale;
            if (mode == 0) {
                *(float2*)(dst + (size_t)row0 * CD + col)       = make_float2(v00, v01);
                *(float2*)(dst + (size_t)(row0 + 8) * CD + col) = make_float2(v10, v11);
            } else {
                const int h = col >> 6;
                const int d = col & 63;
                #pragma unroll
                for (int rr = 0; rr < 2; rr++) {
                    const int row = row0 + rr * 8;
                    const float x0 = rr ? v10 : v00;
                    const float x1 = rr ? v11 : v01;
                    const int bb = row >> 11;
                    const int t  = row & (CT - 1);
                    const size_t idx = ((size_t)((bb * CNH + h) * CT + t)) * 64 + d;
                    __half2 hh = __floats2half2_rn(x0, x1);
                    *(__half2*)(dhi + idx) = hh;
                    if (mode == 1) {
                        __half2 ll = __floats2half2_rn(
                            x0 - __low2float(hh), x1 - __high2float(hh));
                        *(__half2*)(dlo + idx) = ll;
                    }
                }
            }
        }
    }
}

// ---------------------------------------------------------------------------
// fp16 flash attention, ALiBi + causal. 2-term: Q split, K single; P split,
// V single. CTA: 64 q-rows (4 warps), 64-key tiles, double-buffered KV.
// smem: Qhi 8K | Qlo 8K | 2 x (Kh 8K | Vh 8K) = 48KB -> 3 CTAs/SM.
// ---------------------------------------------------------------------------
#define A_QBYTES 16384
#define A_STG    16384
#define ASMEM    (A_QBYTES + 2*A_STG)   // 48KB

static __device__ __forceinline__ uint32_t swz128(int r, int c16) {
    return (uint32_t)(r * 128 + ((c16 ^ (r & 7)) << 4));
}

static __device__ __forceinline__ void a_load_kv(
    uint32_t stg, int tid,
    const __half* __restrict__ kh, const __half* __restrict__ vh, int j0)
{
    #pragma unroll
    for (int i = 0; i < 8; i++) {
        const int id = tid + i * 128;
        const int p = id >> 9;               // 0 = K, 1 = V
        const int inner = id & 511;
        const int r = inner >> 3, c = inner & 7;
        cp16(stg + (uint32_t)p * 8192 + swz128(r, c),
             (p ? vh : kh) + (size_t)(j0 + r) * 64 + c * 8);
    }
}

__global__ __launch_bounds__(128, 3)
void attn_mma(const __half* __restrict__ qh_, const __half* __restrict__ ql_,
              const __half* __restrict__ kh_, const __half* __restrict__ vh_,
              __half* __restrict__ ohi, __half* __restrict__ olo)
{
    extern __shared__ char dsm[];
    const uint32_t sb = smem_u32(dsm);
    const uint32_t sqh = sb, sql = sb + 8192;
    const uint32_t stg0 = sb + A_QBYTES, stg1 = stg0 + A_STG;

    const int tid  = threadIdx.x;
    const int lane = tid & 31;
    const int w    = tid >> 5;
    const int tq   = 31 - (int)blockIdx.x;     // longest CTAs first
    const int h    = blockIdx.y;
    const int b    = blockIdx.z;
    const int i0   = tq * 64;
    const int njt  = tq + 1;

    const size_t base = (size_t)(b * CNH + h) * CT * 64;
    const __half* qh = qh_ + base; const __half* ql = ql_ + base;
    const __half* kh = kh_ + base; const __half* vh = vh_ + base;

    const float slope = exp2f(-0.5f * (float)(h + 1));

    // Q tile load (qh + ql)
    #pragma unroll
    for (int i = 0; i < 8; i++) {
        const int id = tid + i * 128;
        const int hl = id >> 9;
        const int inner = id & 511;
        const int r = inner >> 3, c = inner & 7;
        cp16((hl ? sql : sqh) + swz128(r, c),
             (hl ? ql : qh) + (size_t)(i0 + r) * 64 + c * 8);
    }
    cp_commit();
    a_load_kv(stg0, tid, kh, vh, 0);
    cp_commit();

    cp_wait<1>();          // Q ready
    __syncthreads();

    const int lr = lane & 15;
    const int lc = lane >> 4;
    uint32_t qfh[4][4], qfl[4][4];
    #pragma unroll
    for (int kk = 0; kk < 4; kk++) {
        const int r = w * 16 + lr;
        ldsm4(qfh[kk][0], qfh[kk][1], qfh[kk][2], qfh[kk][3], sqh + swz128(r, kk*2 + lc));
        ldsm4(qfl[kk][0], qfl[kk][1], qfl[kk][2], qfl[kk][3], sql + swz128(r, kk*2 + lc));
    }

    const int qr = lane >> 2;
    const int qc = (lane & 3) * 2;
    const int irow0 = i0 + w * 16 + qr;
    const int irow1 = irow0 + 8;

    float O[8][4];
    #pragma unroll
    for (int nj = 0; nj < 8; nj++)
        #pragma unroll
        for (int e = 0; e < 4; e++) O[nj][e] = 0.f;
    float m0 = -1e30f, m1 = -1e30f, l0 = 0.f, l1 = 0.f;

    for (int jt = 0; jt < njt; jt++) {
        if (jt + 1 < njt) {
            a_load_kv((jt & 1) ? stg0 : stg1, tid, kh, vh, (jt + 1) * 64);
            cp_commit();
            cp_wait<1>();
        } else {
            cp_wait<0>();
        }
        __syncthreads();

        const uint32_t stg = (jt & 1) ? stg1 : stg0;
        const uint32_t skh = stg, svh = stg + 8192;

        // ---- S = (Qh+Ql) K^T ----
        float S[8][4];
        #pragma unroll
        for (int nj = 0; nj < 8; nj++)
            #pragma unroll
            for (int e = 0; e < 4; e++) S[nj][e] = 0.f;

        #pragma unroll
        for (int kk = 0; kk < 4; kk++) {
            #pragma unroll
            for (int n16 = 0; n16 < 4; n16++) {
                const int r = n16 * 16 + lr;
                uint32_t h0, h1, h2, h3;
                ldsm4(h0, h1, h2, h3, skh + swz128(r, kk*2 + lc));
                mma16816(S[n16*2],   qfh[kk], h0, h2);
                mma16816(S[n16*2],   qfl[kk], h0, h2);
                mma16816(S[n16*2+1], qfh[kk], h1, h3);
                mma16816(S[n16*2+1], qfl[kk], h1, h3);
            }
        }

        // ---- ALiBi + causal + online softmax ----
        const int jbase = jt * 64;
        const bool lastt = (jt == njt - 1);
        float tmax0 = -1e30f, tmax1 = -1e30f;
        #pragma unroll
        for (int nj = 0; nj < 8; nj++) {
            const int j0c = jbase + nj * 8 + qc;
            #pragma unroll
            for (int e = 0; e < 4; e++) {
                const int j = j0c + (e & 1);
                const int i = (e >> 1) ? irow1 : irow0;
                float s = S[nj][e] + slope * (float)(j - i);
                if (lastt && j > i) s = -1e30f;
                S[nj][e] = s;
            }
            tmax0 = fmaxf(tmax0, fmaxf(S[nj][0], S[nj][1]));
            tmax1 = fmaxf(tmax1, fmaxf(S[nj][2], S[nj][3]));
        }
        tmax0 = fmaxf(tmax0, __shfl_xor_sync(0xFFFFFFFFu, tmax0, 1));
        tmax0 = fmaxf(tmax0, __shfl_xor_sync(0xFFFFFFFFu, tmax0, 2));
        tmax1 = fmaxf(tmax1, __shfl_xor_sync(0xFFFFFFFFu, tmax1, 1));
        tmax1 = fmaxf(tmax1, __shfl_xor_sync(0xFFFFFFFFu, tmax1, 2));

        const float mn0 = fmaxf(m0, tmax0);
        const float mn1 = fmaxf(m1, tmax1);
        const float cr0 = __expf(m0 - mn0);
        const float cr1 = __expf(m1 - mn1);
        m0 = mn0; m1 = mn1;

        float ls0 = 0.f, ls1 = 0.f;
        #pragma unroll
        for (int nj = 0; nj < 8; nj++) {
            S[nj][0] = __expf(S[nj][0] - mn0);
            S[nj][1] = __expf(S[nj][1] - mn0);
            S[nj][2] = __expf(S[nj][2] - mn1);
            S[nj][3] = __expf(S[nj][3] - mn1);
            ls0 += S[nj][0] + S[nj][1];
            ls1 += S[nj][2] + S[nj][3];
        }
        l0 = l0 * cr0 + ls0;
        l1 = l1 * cr1 + ls1;
        #pragma unroll
        for (int nj = 0; nj < 8; nj++) {
            O[nj][0] *= cr0; O[nj][1] *= cr0;
            O[nj][2] *= cr1; O[nj][3] *= cr1;
        }

        // ---- O += (Ph+Pl) V ----
        #pragma unroll
        for (int kk = 0; kk < 4; kk++) {
            uint32_t ph[4], pl[4];
            {
                const float* sA = S[2*kk];
                const float* sB = S[2*kk + 1];
                __half2 h2, l2;
                h2 = __floats2half2_rn(sA[0], sA[1]);
                l2 = __floats2half2_rn(sA[0] - __low2float(h2), sA[1] - __high2float(h2));
                ph[0] = *(uint32_t*)&h2; pl[0] = *(uint32_t*)&l2;
                h2 = __floats2half2_rn(sA[2], sA[3]);
                l2 = __floats2half2_rn(sA[2] - __low2float(h2), sA[3] - __high2float(h2));
                ph[1] = *(uint32_t*)&h2; pl[1] = *(uint32_t*)&l2;
                h2 = __floats2half2_rn(sB[0], sB[1]);
                l2 = __floats2half2_rn(sB[0] - __low2float(h2), sB[1] - __high2float(h2));
                ph[2] = *(uint32_t*)&h2; pl[2] = *(uint32_t*)&l2;
                h2 = __floats2half2_rn(sB[2], sB[3]);
                l2 = __floats2half2_rn(sB[2] - __low2float(h2), sB[3] - __high2float(h2));
                ph[3] = *(uint32_t*)&h2; pl[3] = *(uint32_t*)&l2;
            }
            #pragma unroll
            for (int n16 = 0; n16 < 4; n16++) {
                const int r = kk * 16 + lr;
                uint32_t v0, v1, v2, v3;
                ldsm4t(v0, v1, v2, v3, svh + swz128(r, n16*2 + lc));
                mma16816(O[n16*2],   ph, v0, v1);
                mma16816(O[n16*2],   pl, v0, v1);
                mma16816(O[n16*2+1], ph, v2, v3);
                mma16816(O[n16*2+1], pl, v2, v3);
            }
        }
        __syncthreads();
    }

    // ---- normalize + hi/lo store (A operand of output projection) ----
    l0 += __shfl_xor_sync(0xFFFFFFFFu, l0, 1);
    l0 += __shfl_xor_sync(0xFFFFFFFFu, l0, 2);
    l1 += __shfl_xor_sync(0xFFFFFFFFu, l1, 1);
    l1 += __shfl_xor_sync(0xFFFFFFFFu, l1, 2);
    const float inv0 = 1.0f / l0;
    const float inv1 = 1.0f / l1;

    #pragma unroll
    for (int nj = 0; nj < 8; nj++) {
        const int col = h * 64 + nj * 8 + qc;
        const size_t idx0 = (size_t)(b * CT + irow0) * CD + col;
        const size_t idx1 = (size_t)(b * CT + irow1) * CD + col;
        float o00 = O[nj][0] * inv0, o01 = O[nj][1] * inv0;
        float o10 = O[nj][2] * inv1, o11 = O[nj][3] * inv1;
        __half2 h2, l2;
        h2 = __floats2half2_rn(o00, o01);
        l2 = __floats2half2_rn(o00 - __low2float(h2), o01 - __high2float(h2));
        *(__half2*)(ohi + idx0) = h2;
        *(__half2*)(olo + idx0) = l2;
        h2 = __floats2half2_rn(o10, o11);
        l2 = __floats2half2_rn(o10 - __low2float(h2), o11 - __high2float(h2));
        *(__half2*)(ohi + idx1) = h2;
        *(__half2*)(olo + idx1) = l2;
    }
}

// ---------------------------------------------------------------------------
extern "C" void kernel_launch(void* const* d_in, const int* in_sizes, int n_in,
                              void* d_out, int out_size)
{
    (void)in_sizes; (void)n_in; (void)out_size;
    const float* x  = (const float*)d_in[0];
    const float* Wq = (const float*)d_in[1];
    const float* bq = (const float*)d_in[2];
    const float* Wk = (const float*)d_in[3];
    const float* bk = (const float*)d_in[4];
    const float* Wv = (const float*)d_in[5];
    const float* bv = (const float*)d_in[6];
    const float* Wp = (const float*)d_in[7];
    const float* bp = (const float*)d_in[8];

    __half *ahi, *alo, *wh, *qh, *ql, *kh, *vh;
    cudaGetSymbolAddress((void**)&ahi, g_ahi);
    cudaGetSymbolAddress((void**)&alo, g_alo);
    cudaGetSymbolAddress((void**)&wh,  g_wh);
    cudaGetSymbolAddress((void**)&qh,  g_qh);
    cudaGetSymbolAddress((void**)&ql,  g_ql);
    cudaGetSymbolAddress((void**)&kh,  g_kh);
    cudaGetSymbolAddress((void**)&vh,  g_vh);

    cudaFuncSetAttribute(tc_gemm,  cudaFuncAttributeMaxDynamicSharedMemorySize, GSMEM);
    cudaFuncSetAttribute(attn_mma, cudaFuncAttributeMaxDynamicSharedMemorySize, ASMEM);

    const int WN = CD * CD;
    const float invs = 0.17677669529663687f;   // 1024^(-0.25)

    cvt_split<<<(CM*CD/4 + 255)/256, 256>>>(x, ahi, alo, CM*CD/4);
    cvt_single<<<(WN/4 + 255)/256, 256>>>(Wq, wh + 0*WN, WN/4);
    cvt_single<<<(WN/4 + 255)/256, 256>>>(Wk, wh + 1*WN, WN/4);
    cvt_single<<<(WN/4 + 255)/256, 256>>>(Wv, wh + 2*WN, WN/4);
    cvt_single<<<(WN/4 + 255)/256, 256>>>(Wp, wh + 3*WN, WN/4);

    const dim3 gg(CD / GBN, CM / GBM);   // (8, 32)
    tc_gemm<<<gg, 256, GSMEM>>>(ahi, alo, wh + 0*WN, bq, nullptr, qh, ql, invs, 1);
    tc_gemm<<<gg, 256, GSMEM>>>(ahi, alo, wh + 1*WN, bk, nullptr, kh, nullptr, invs, 2);
    tc_gemm<<<gg, 256, GSMEM>>>(ahi, alo, wh + 2*WN, bv, nullptr, vh, nullptr, 1.0f, 2);

    attn_mma<<<dim3(32, CNH, CB), 128, ASMEM>>>(qh, ql, kh, vh, ahi, alo);

    tc_gemm<<<gg, 256, GSMEM>>>(ahi, alo, wh + 3*WN, bp, (float*)d_out,
                                nullptr, nullptr, 1.0f, 0);
}

// round 9
// speedup vs baseline: 2.2231x; 1.6271x over previous
#include <cuda_runtime.h>
#include <cuda_fp16.h>
#include <cstdint>

// Problem constants
#define CB 2
#define CT 2048
#define CD 1024
#define CNH 16
#define CHD 64
#define CM (CB*CT)              // 4096 rows

// ---------------------------------------------------------------------------
// Scratch (device globals) — all single fp16 now
// ---------------------------------------------------------------------------
__device__ __half g_ah[CM*CD];          // A operand (x, then att out)
__device__ __half g_wh[4*CD*CD];        // weights
__device__ __half g_qh[CM*CD];          // head-major [B,NH,T,64]
__device__ __half g_kh[CM*CD];
__device__ __half g_vh[CM*CD];

// ---------------------------------------------------------------------------
// PTX helpers
// ---------------------------------------------------------------------------
static __device__ __forceinline__ void cp16(uint32_t d, const void* s) {
    asm volatile("cp.async.cg.shared.global [%0], [%1], 16;\n" :: "r"(d), "l"(s));
}
static __device__ __forceinline__ void cp_commit() {
    asm volatile("cp.async.commit_group;\n" ::: "memory");
}
template<int N> static __device__ __forceinline__ void cp_wait() {
    asm volatile("cp.async.wait_group %0;\n" :: "n"(N) : "memory");
}
static __device__ __forceinline__ void ldsm4(uint32_t& r0, uint32_t& r1,
                                             uint32_t& r2, uint32_t& r3, uint32_t a) {
    asm volatile("ldmatrix.sync.aligned.m8n8.x4.shared.b16 {%0,%1,%2,%3}, [%4];"
                 : "=r"(r0), "=r"(r1), "=r"(r2), "=r"(r3) : "r"(a));
}
static __device__ __forceinline__ void ldsm4t(uint32_t& r0, uint32_t& r1,
                                              uint32_t& r2, uint32_t& r3, uint32_t a) {
    asm volatile("ldmatrix.sync.aligned.m8n8.x4.trans.shared.b16 {%0,%1,%2,%3}, [%4];"
                 : "=r"(r0), "=r"(r1), "=r"(r2), "=r"(r3) : "r"(a));
}
static __device__ __forceinline__ void mma16816(float* c, const uint32_t* a,
                                                uint32_t b0, uint32_t b1) {
    asm volatile(
        "mma.sync.aligned.m16n8k16.row.col.f32.f16.f16.f32 "
        "{%0,%1,%2,%3}, {%4,%5,%6,%7}, {%8,%9}, {%0,%1,%2,%3};"
        : "+f"(c[0]), "+f"(c[1]), "+f"(c[2]), "+f"(c[3])
        : "r"(a[0]), "r"(a[1]), "r"(a[2]), "r"(a[3]), "r"(b0), "r"(b1));
}
static __device__ __forceinline__ uint32_t smem_u32(const void* p) {
    uint32_t r;
    asm("{ .reg .u64 t; cvta.to.shared.u64 t, %1; cvt.u32.u64 %0, t; }" : "=r"(r) : "l"(p));
    return r;
}

// ---------------------------------------------------------------------------
// fp32 -> fp16 single
// ---------------------------------------------------------------------------
__global__ __launch_bounds__(256)
void cvt_single(const float* __restrict__ s, __half* __restrict__ d, int n4)
{
    int i = blockIdx.x * blockDim.x + threadIdx.x;
    if (i >= n4) return;
    float4 v = ((const float4*)s)[i];
    ((__half2*)d)[2*i]   = __floats2half2_rn(v.x, v.y);
    ((__half2*)d)[2*i+1] = __floats2half2_rn(v.z, v.w);
}

// ---------------------------------------------------------------------------
// mma.sync fp16 GEMM: C = A @ B^T (single term).
// mode 0: out = (C+bias)*scale fp32 row-major [CM,CD]
// mode 2: out = (C+bias)*scale fp16 head-major [B,NH,T,64]
// Stage = A|B = 16KB; 3 stages = 48KB -> 2 CTAs/SM (reg-limited).
// ---------------------------------------------------------------------------
#define GBM 128
#define GBN 128
#define GBK 32
#define GSTAGES 3
#define GNKT (CD/GBK)
#define PART_BYTES 8192
#define STG_BYTES (2*PART_BYTES)       // 16KB
#define GSMEM (GSTAGES*STG_BYTES)      // 48KB

static __device__ __forceinline__ uint32_t swz(int r, int c16) {
    return (uint32_t)(r * 64 + ((c16 ^ ((r >> 1) & 3)) << 4));
}

static __device__ __forceinline__ void g_load_stage(
    uint32_t sbase, int kt, int tid,
    const __half* __restrict__ Ah, const __half* __restrict__ Bh,
    int bm, int bn)
{
    const int k0 = kt * GBK;
    #pragma unroll
    for (int i = 0; i < 4; i++) {
        const int id = tid + i * 256;          // 0..1023
        const int p = id >> 9;                 // 0 = A, 1 = B
        const int inner = id & 511;
        const int r = inner >> 2;
        const int c = inner & 3;
        const int rowbase = p ? bn : bm;
        cp16(sbase + (uint32_t)p * PART_BYTES + swz(r, c),
             (p ? Bh : Ah) + (size_t)(rowbase + r) * CD + k0 + c * 8);
    }
}

__global__ __launch_bounds__(256, 2)
void tc_gemm(const __half* __restrict__ Ah, const __half* __restrict__ Bh,
             const float* __restrict__ bias, float* __restrict__ dst,
             __half* __restrict__ dsth, float scale, int mode)
{
    extern __shared__ char dsm[];
    uint32_t sb = smem_u32(dsm);

    const int tid  = threadIdx.x;
    const int wid  = tid >> 5;
    const int lane = tid & 31;
    const int bm   = blockIdx.y * GBM;
    const int bn   = blockIdx.x * GBN;
    const int m0w  = (wid & 3) * 32;
    const int n0w  = (wid >> 2) * 64;

    float acc[2][8][4];
    #pragma unroll
    for (int i = 0; i < 2; i++)
        #pragma unroll
        for (int j = 0; j < 8; j++)
            #pragma unroll
            for (int k = 0; k < 4; k++) acc[i][j][k] = 0.f;

    #pragma unroll
    for (int s = 0; s < GSTAGES - 1; s++) {
        g_load_stage(sb + s * STG_BYTES, s, tid, Ah, Bh, bm, bn);
        cp_commit();
    }

    const int lr = lane & 15;
    const int lc = lane >> 4;

    for (int kt = 0; kt < GNKT; kt++) {
        cp_wait<1>();
        __syncthreads();

        if (kt + 2 < GNKT) {
            g_load_stage(sb + ((kt + 2) % GSTAGES) * STG_BYTES,
                         kt + 2, tid, Ah, Bh, bm, bn);
        }
        cp_commit();

        const uint32_t stg = sb + (uint32_t)(kt % GSTAGES) * STG_BYTES;
        #pragma unroll
        for (int ks = 0; ks < 2; ks++) {
            const int c16 = 2 * ks + lc;
            uint32_t a0[2][4];
            #pragma unroll
            for (int mi = 0; mi < 2; mi++) {
                const int r = m0w + mi * 16 + lr;
                ldsm4(a0[mi][0], a0[mi][1], a0[mi][2], a0[mi][3],
                      stg + swz(r, c16));
            }
            #pragma unroll
            for (int bj = 0; bj < 4; bj++) {
                const int r = n0w + bj * 16 + lr;
                uint32_t h0, h1, h2, h3;
                ldsm4(h0, h1, h2, h3, stg + PART_BYTES + swz(r, c16));
                #pragma unroll
                for (int mi = 0; mi < 2; mi++) {
                    mma16816(acc[mi][bj*2],   a0[mi], h0, h2);
                    mma16816(acc[mi][bj*2+1], a0[mi], h1, h3);
                }
            }
        }
    }

    const int qr = lane >> 2;
    const int qc = (lane & 3) * 2;
    #pragma unroll
    for (int mi = 0; mi < 2; mi++) {
        #pragma unroll
        for (int nj = 0; nj < 8; nj++) {
            const int col = bn + n0w + nj * 8 + qc;
            const float b0 = __ldg(bias + col);
            const float b1 = __ldg(bias + col + 1);
            const int row0 = bm + m0w + mi * 16 + qr;
            float v00 = (acc[mi][nj][0] + b0) * scale;
            float v01 = (acc[mi][nj][1] + b1) * scale;
            float v10 = (acc[mi][nj][2] + b0) * scale;
            float v11 = (acc[mi][nj][3] + b1) * scale;
            if (mode == 0) {
                *(float2*)(dst + (size_t)row0 * CD + col)       = make_float2(v00, v01);
                *(float2*)(dst + (size_t)(row0 + 8) * CD + col) = make_float2(v10, v11);
            } else {
                const int h = col >> 6;
                const int d = col & 63;
                #pragma unroll
                for (int rr = 0; rr < 2; rr++) {
                    const int row = row0 + rr * 8;
                    const float x0 = rr ? v10 : v00;
                    const float x1 = rr ? v11 : v01;
                    const int bb = row >> 11;
                    const int t  = row & (CT - 1);
                    const size_t idx = ((size_t)((bb * CNH + h) * CT + t)) * 64 + d;
                    *(__half2*)(dsth + idx) = __floats2half2_rn(x0, x1);
                }
            }
        }
    }
}

// ---------------------------------------------------------------------------
// fp16 flash attention, ALiBi + causal, single term everywhere.
// CTA: 64 q-rows (4 warps), 64-key tiles, double-buffered KV.
// smem: Q 8K | 2 x (K 8K | V 8K) = 40KB -> 3 CTAs/SM.
// ---------------------------------------------------------------------------
#define A_QBYTES 8192
#define A_STG    16384
#define ASMEM    (A_QBYTES + 2*A_STG)   // 40KB

static __device__ __forceinline__ uint32_t swz128(int r, int c16) {
    return (uint32_t)(r * 128 + ((c16 ^ (r & 7)) << 4));
}

static __device__ __forceinline__ void a_load_kv(
    uint32_t stg, int tid,
    const __half* __restrict__ kh, const __half* __restrict__ vh, int j0)
{
    #pragma unroll
    for (int i = 0; i < 8; i++) {
        const int id = tid + i * 128;
        const int p = id >> 9;               // 0 = K, 1 = V
        const int inner = id & 511;
        const int r = inner >> 3, c = inner & 7;
        cp16(stg + (uint32_t)p * 8192 + swz128(r, c),
             (p ? vh : kh) + (size_t)(j0 + r) * 64 + c * 8);
    }
}

__global__ __launch_bounds__(128, 3)
void attn_mma(const __half* __restrict__ qh_, const __half* __restrict__ kh_,
              const __half* __restrict__ vh_, __half* __restrict__ oh)
{
    extern __shared__ char dsm[];
    const uint32_t sb = smem_u32(dsm);
    const uint32_t sqh = sb;
    const uint32_t stg0 = sb + A_QBYTES, stg1 = stg0 + A_STG;

    const int tid  = threadIdx.x;
    const int lane = tid & 31;
    const int w    = tid >> 5;
    const int tq   = 31 - (int)blockIdx.x;     // longest CTAs first
    const int h    = blockIdx.y;
    const int b    = blockIdx.z;
    const int i0   = tq * 64;
    const int njt  = tq + 1;

    const size_t base = (size_t)(b * CNH + h) * CT * 64;
    const __half* qh = qh_ + base;
    const __half* kh = kh_ + base;
    const __half* vh = vh_ + base;

    const float slope = exp2f(-0.5f * (float)(h + 1));

    // Q tile load (64 rows x 128B = 512 chunks)
    #pragma unroll
    for (int i = 0; i < 4; i++) {
        const int id = tid + i * 128;
        const int r = id >> 3, c = id & 7;
        cp16(sqh + swz128(r, c), qh + (size_t)(i0 + r) * 64 + c * 8);
    }
    cp_commit();
    a_load_kv(stg0, tid, kh, vh, 0);
    cp_commit();

    cp_wait<1>();          // Q ready
    __syncthreads();

    const int lr = lane & 15;
    const int lc = lane >> 4;
    uint32_t qf[4][4];
    #pragma unroll
    for (int kk = 0; kk < 4; kk++) {
        const int r = w * 16 + lr;
        ldsm4(qf[kk][0], qf[kk][1], qf[kk][2], qf[kk][3], sqh + swz128(r, kk*2 + lc));
    }

    const int qr = lane >> 2;
    const int qc = (lane & 3) * 2;
    const int irow0 = i0 + w * 16 + qr;
    const int irow1 = irow0 + 8;

    float O[8][4];
    #pragma unroll
    for (int nj = 0; nj < 8; nj++)
        #pragma unroll
        for (int e = 0; e < 4; e++) O[nj][e] = 0.f;
    float m0 = -1e30f, m1 = -1e30f, l0 = 0.f, l1 = 0.f;

    for (int jt = 0; jt < njt; jt++) {
        if (jt + 1 < njt) {
            a_load_kv((jt & 1) ? stg0 : stg1, tid, kh, vh, (jt + 1) * 64);
            cp_commit();
            cp_wait<1>();
        } else {
            cp_wait<0>();
        }
        __syncthreads();

        const uint32_t stg = (jt & 1) ? stg1 : stg0;
        const uint32_t skh = stg, svh = stg + 8192;

        // ---- S = Q K^T ----
        float S[8][4];
        #pragma unroll
        for (int nj = 0; nj < 8; nj++)
            #pragma unroll
            for (int e = 0; e < 4; e++) S[nj][e] = 0.f;

        #pragma unroll
        for (int kk = 0; kk < 4; kk++) {
            #pragma unroll
            for (int n16 = 0; n16 < 4; n16++) {
                const int r = n16 * 16 + lr;
                uint32_t h0, h1, h2, h3;
                ldsm4(h0, h1, h2, h3, skh + swz128(r, kk*2 + lc));
                mma16816(S[n16*2],   qf[kk], h0, h2);
                mma16816(S[n16*2+1], qf[kk], h1, h3);
            }
        }

        // ---- ALiBi + causal + online softmax ----
        const int jbase = jt * 64;
        const bool lastt = (jt == njt - 1);
        float tmax0 = -1e30f, tmax1 = -1e30f;
        #pragma unroll
        for (int nj = 0; nj < 8; nj++) {
            const int j0c = jbase + nj * 8 + qc;
            #pragma unroll
            for (int e = 0; e < 4; e++) {
                const int j = j0c + (e & 1);
                const int i = (e >> 1) ? irow1 : irow0;
                float s = S[nj][e] + slope * (float)(j - i);
                if (lastt && j > i) s = -1e30f;
                S[nj][e] = s;
            }
            tmax0 = fmaxf(tmax0, fmaxf(S[nj][0], S[nj][1]));
            tmax1 = fmaxf(tmax1, fmaxf(S[nj][2], S[nj][3]));
        }
        tmax0 = fmaxf(tmax0, __shfl_xor_sync(0xFFFFFFFFu, tmax0, 1));
        tmax0 = fmaxf(tmax0, __shfl_xor_sync(0xFFFFFFFFu, tmax0, 2));
        tmax1 = fmaxf(tmax1, __shfl_xor_sync(0xFFFFFFFFu, tmax1, 1));
        tmax1 = fmaxf(tmax1, __shfl_xor_sync(0xFFFFFFFFu, tmax1, 2));

        const float mn0 = fmaxf(m0, tmax0);
        const float mn1 = fmaxf(m1, tmax1);
        const float cr0 = __expf(m0 - mn0);
        const float cr1 = __expf(m1 - mn1);
        m0 = mn0; m1 = mn1;

        float ls0 = 0.f, ls1 = 0.f;
        #pragma unroll
        for (int nj = 0; nj < 8; nj++) {
            S[nj][0] = __expf(S[nj][0] - mn0);
            S[nj][1] = __expf(S[nj][1] - mn0);
            S[nj][2] = __expf(S[nj][2] - mn1);
            S[nj][3] = __expf(S[nj][3] - mn1);
            ls0 += S[nj][0] + S[nj][1];
            ls1 += S[nj][2] + S[nj][3];
        }
        l0 = l0 * cr0 + ls0;
        l1 = l1 * cr1 + ls1;
        #pragma unroll
        for (int nj = 0; nj < 8; nj++) {
            O[nj][0] *= cr0; O[nj][1] *= cr0;
            O[nj][2] *= cr1; O[nj][3] *= cr1;
        }

        // ---- O += P V ----
        #pragma unroll
        for (int kk = 0; kk < 4; kk++) {
            uint32_t ph[4];
            {
                const float* sA = S[2*kk];
                const float* sB = S[2*kk + 1];
                __half2 t;
                t = __floats2half2_rn(sA[0], sA[1]); ph[0] = *(uint32_t*)&t;
                t = __floats2half2_rn(sA[2], sA[3]); ph[1] = *(uint32_t*)&t;
                t = __floats2half2_rn(sB[0], sB[1]); ph[2] = *(uint32_t*)&t;
                t = __floats2half2_rn(sB[2], sB[3]); ph[3] = *(uint32_t*)&t;
            }
            #pragma unroll
            for (int n16 = 0; n16 < 4; n16++) {
                const int r = kk * 16 + lr;
                uint32_t v0, v1, v2, v3;
                ldsm4t(v0, v1, v2, v3, svh + swz128(r, n16*2 + lc));
                mma16816(O[n16*2],   ph, v0, v1);
                mma16816(O[n16*2+1], ph, v2, v3);
            }
        }
        __syncthreads();
    }

    // ---- normalize + fp16 store (A operand of output projection) ----
    l0 += __shfl_xor_sync(0xFFFFFFFFu, l0, 1);
    l0 += __shfl_xor_sync(0xFFFFFFFFu, l0, 2);
    l1 += __shfl_xor_sync(0xFFFFFFFFu, l1, 1);
    l1 += __shfl_xor_sync(0xFFFFFFFFu, l1, 2);
    const float inv0 = 1.0f / l0;
    const float inv1 = 1.0f / l1;

    #pragma unroll
    for (int nj = 0; nj < 8; nj++) {
        const int col = h * 64 + nj * 8 + qc;
        const size_t idx0 = (size_t)(b * CT + irow0) * CD + col;
        const size_t idx1 = (size_t)(b * CT + irow1) * CD + col;
        *(__half2*)(oh + idx0) = __floats2half2_rn(O[nj][0] * inv0, O[nj][1] * inv0);
        *(__half2*)(oh + idx1) = __floats2half2_rn(O[nj][2] * inv1, O[nj][3] * inv1);
    }
}

// ---------------------------------------------------------------------------
extern "C" void kernel_launch(void* const* d_in, const int* in_sizes, int n_in,
                              void* d_out, int out_size)
{
    (void)in_sizes; (void)n_in; (void)out_size;
    const float* x  = (const float*)d_in[0];
    const float* Wq = (const float*)d_in[1];
    const float* bq = (const float*)d_in[2];
    const float* Wk = (const float*)d_in[3];
    const float* bk = (const float*)d_in[4];
    const float* Wv = (const float*)d_in[5];
    const float* bv = (const float*)d_in[6];
    const float* Wp = (const float*)d_in[7];
    const float* bp = (const float*)d_in[8];

    __half *ah, *wh, *qh, *kh, *vh;
    cudaGetSymbolAddress((void**)&ah, g_ah);
    cudaGetSymbolAddress((void**)&wh, g_wh);
    cudaGetSymbolAddress((void**)&qh, g_qh);
    cudaGetSymbolAddress((void**)&kh, g_kh);
    cudaGetSymbolAddress((void**)&vh, g_vh);

    cudaFuncSetAttribute(tc_gemm,  cudaFuncAttributeMaxDynamicSharedMemorySize, GSMEM);
    cudaFuncSetAttribute(attn_mma, cudaFuncAttributeMaxDynamicSharedMemorySize, ASMEM);

    const int WN = CD * CD;
    const float invs = 0.17677669529663687f;   // 1024^(-0.25)

    cvt_single<<<(CM*CD/4 + 255)/256, 256>>>(x, ah, CM*CD/4);
    cvt_single<<<(WN/4 + 255)/256, 256>>>(Wq, wh + 0*WN, WN/4);
    cvt_single<<<(WN/4 + 255)/256, 256>>>(Wk, wh + 1*WN, WN/4);
    cvt_single<<<(WN/4 + 255)/256, 256>>>(Wv, wh + 2*WN, WN/4);
    cvt_single<<<(WN/4 + 255)/256, 256>>>(Wp, wh + 3*WN, WN/4);

    const dim3 gg(CD / GBN, CM / GBM);   // (8, 32)
    tc_gemm<<<gg, 256, GSMEM>>>(ah, wh + 0*WN, bq, nullptr, qh, invs, 2);
    tc_gemm<<<gg, 256, GSMEM>>>(ah, wh + 1*WN, bk, nullptr, kh, invs, 2);
    tc_gemm<<<gg, 256, GSMEM>>>(ah, wh + 2*WN, bv, nullptr, vh, 1.0f, 2);

    attn_mma<<<dim3(32, CNH, CB), 128, ASMEM>>>(qh, kh, vh, ah);

    tc_gemm<<<gg, 256, GSMEM>>>(ah, wh + 3*WN, bp, (float*)d_out,
                                nullptr, 1.0f, 0);
}

// round 10
// speedup vs baseline: 2.5392x; 1.1422x over previous
#include <cuda_runtime.h>
#include <cuda_fp16.h>
#include <cstdint>

// Problem constants
#define CB 2
#define CT 2048
#define CD 1024
#define CNH 16
#define CHD 64
#define CM (CB*CT)              // 4096 rows

// ---------------------------------------------------------------------------
// Scratch (device globals)
// ---------------------------------------------------------------------------
__device__ __half g_ah[CM*CD];          // A operand (x, then att out)
__device__ __half g_wh[4*CD*CD];        // Wq|Wk|Wv|Wp stacked, fp16
__device__ __half g_qh[CM*CD];          // head-major [B,NH,T,64]
__device__ __half g_kh[CM*CD];
__device__ __half g_vh[CM*CD];

// ---------------------------------------------------------------------------
// PTX helpers
// ---------------------------------------------------------------------------
static __device__ __forceinline__ void cp16(uint32_t d, const void* s) {
    asm volatile("cp.async.cg.shared.global [%0], [%1], 16;\n" :: "r"(d), "l"(s));
}
static __device__ __forceinline__ void cp_commit() {
    asm volatile("cp.async.commit_group;\n" ::: "memory");
}
template<int N> static __device__ __forceinline__ void cp_wait() {
    asm volatile("cp.async.wait_group %0;\n" :: "n"(N) : "memory");
}
static __device__ __forceinline__ void ldsm4(uint32_t& r0, uint32_t& r1,
                                             uint32_t& r2, uint32_t& r3, uint32_t a) {
    asm volatile("ldmatrix.sync.aligned.m8n8.x4.shared.b16 {%0,%1,%2,%3}, [%4];"
                 : "=r"(r0), "=r"(r1), "=r"(r2), "=r"(r3) : "r"(a));
}
static __device__ __forceinline__ void ldsm4t(uint32_t& r0, uint32_t& r1,
                                              uint32_t& r2, uint32_t& r3, uint32_t a) {
    asm volatile("ldmatrix.sync.aligned.m8n8.x4.trans.shared.b16 {%0,%1,%2,%3}, [%4];"
                 : "=r"(r0), "=r"(r1), "=r"(r2), "=r"(r3) : "r"(a));
}
static __device__ __forceinline__ void mma16816(float* c, const uint32_t* a,
                                                uint32_t b0, uint32_t b1) {
    asm volatile(
        "mma.sync.aligned.m16n8k16.row.col.f32.f16.f16.f32 "
        "{%0,%1,%2,%3}, {%4,%5,%6,%7}, {%8,%9}, {%0,%1,%2,%3};"
        : "+f"(c[0]), "+f"(c[1]), "+f"(c[2]), "+f"(c[3])
        : "r"(a[0]), "r"(a[1]), "r"(a[2]), "r"(a[3]), "r"(b0), "r"(b1));
}
static __device__ __forceinline__ uint32_t smem_u32(const void* p) {
    uint32_t r;
    asm("{ .reg .u64 t; cvta.to.shared.u64 t, %1; cvt.u32.u64 %0, t; }" : "=r"(r) : "l"(p));
    return r;
}

// ---------------------------------------------------------------------------
// fp32 -> fp16 conversions (x single launch; all 4 weights in one launch)
// ---------------------------------------------------------------------------
__global__ __launch_bounds__(256)
void cvt_single(const float* __restrict__ s, __half* __restrict__ d, int n4)
{
    int i = blockIdx.x * blockDim.x + threadIdx.x;
    if (i >= n4) return;
    float4 v = ((const float4*)s)[i];
    ((__half2*)d)[2*i]   = __floats2half2_rn(v.x, v.y);
    ((__half2*)d)[2*i+1] = __floats2half2_rn(v.z, v.w);
}

#define W_N4 (CD*CD/4)                 // 262144 = 2^18 float4 per weight
__global__ __launch_bounds__(256)
void cvt_w4(const float* __restrict__ s0, const float* __restrict__ s1,
            const float* __restrict__ s2, const float* __restrict__ s3,
            __half* __restrict__ d)
{
    int i = blockIdx.x * blockDim.x + threadIdx.x;
    if (i >= 4 * W_N4) return;
    const int p = i >> 18;
    const int j = i & (W_N4 - 1);
    const float* s = (p == 0) ? s0 : (p == 1) ? s1 : (p == 2) ? s2 : s3;
    float4 v = ((const float4*)s)[j];
    ((__half2*)d)[2*i]   = __floats2half2_rn(v.x, v.y);
    ((__half2*)d)[2*i+1] = __floats2half2_rn(v.z, v.w);
}

// ---------------------------------------------------------------------------
// mma.sync fp16 GEMM: C = A @ B^T.
// mode 0: out = (C+bias0)*1 fp32 row-major [CM,CD]  (output projection)
// mode 1: fused QKV: N=3072; per-CTA p=bn>>10 selects {q,k,v} dst/bias/scale,
//         out fp16 head-major [B,NH,T,64]
// 4 stages x 16KB = 64KB smem -> 2 CTAs/SM.
// ---------------------------------------------------------------------------
#define GBM 128
#define GBN 128
#define GBK 32
#define GSTAGES 4
#define GNKT (CD/GBK)
#define PART_BYTES 8192
#define STG_BYTES (2*PART_BYTES)       // 16KB
#define GSMEM (GSTAGES*STG_BYTES)      // 64KB

static __device__ __forceinline__ uint32_t swz(int r, int c16) {
    return (uint32_t)(r * 64 + ((c16 ^ ((r >> 1) & 3)) << 4));
}

static __device__ __forceinline__ void g_load_stage(
    uint32_t sbase, int kt, int tid,
    const __half* __restrict__ Ah, const __half* __restrict__ Bh,
    int bm, int bn)
{
    const int k0 = kt * GBK;
    #pragma unroll
    for (int i = 0; i < 4; i++) {
        const int id = tid + i * 256;          // 0..1023
        const int p = id >> 9;                 // 0 = A, 1 = B
        const int inner = id & 511;
        const int r = inner >> 2;
        const int c = inner & 3;
        const int rowbase = p ? bn : bm;
        cp16(sbase + (uint32_t)p * PART_BYTES + swz(r, c),
             (p ? Bh : Ah) + (size_t)(rowbase + r) * CD + k0 + c * 8);
    }
}

__global__ __launch_bounds__(256, 2)
void tc_gemm(const __half* __restrict__ Ah, const __half* __restrict__ Bh,
             const float* __restrict__ bias0, const float* __restrict__ bias1,
             const float* __restrict__ bias2,
             float* __restrict__ dstf,
             __half* __restrict__ dq, __half* __restrict__ dk,
             __half* __restrict__ dv,
             float invs, int mode)
{
    extern __shared__ char dsm[];
    uint32_t sb = smem_u32(dsm);

    const int tid  = threadIdx.x;
    const int wid  = tid >> 5;
    const int lane = tid & 31;
    const int bm   = blockIdx.y * GBM;
    const int bn   = blockIdx.x * GBN;
    const int m0w  = (wid & 3) * 32;
    const int n0w  = (wid >> 2) * 64;

    float acc[2][8][4];
    #pragma unroll
    for (int i = 0; i < 2; i++)
        #pragma unroll
        for (int j = 0; j < 8; j++)
            #pragma unroll
            for (int k = 0; k < 4; k++) acc[i][j][k] = 0.f;

    #pragma unroll
    for (int s = 0; s < GSTAGES - 1; s++) {
        g_load_stage(sb + s * STG_BYTES, s, tid, Ah, Bh, bm, bn);
        cp_commit();
    }

    const int lr = lane & 15;
    const int lc = lane >> 4;

    for (int kt = 0; kt < GNKT; kt++) {
        cp_wait<GSTAGES - 2>();
        __syncthreads();

        if (kt + GSTAGES - 1 < GNKT) {
            g_load_stage(sb + ((kt + GSTAGES - 1) % GSTAGES) * STG_BYTES,
                         kt + GSTAGES - 1, tid, Ah, Bh, bm, bn);
        }
        cp_commit();

        const uint32_t stg = sb + (uint32_t)(kt % GSTAGES) * STG_BYTES;
        #pragma unroll
        for (int ks = 0; ks < 2; ks++) {
            const int c16 = 2 * ks + lc;
            uint32_t a0[2][4];
            #pragma unroll
            for (int mi = 0; mi < 2; mi++) {
                const int r = m0w + mi * 16 + lr;
                ldsm4(a0[mi][0], a0[mi][1], a0[mi][2], a0[mi][3],
                      stg + swz(r, c16));
            }
            #pragma unroll
            for (int bj = 0; bj < 4; bj++) {
                const int r = n0w + bj * 16 + lr;
                uint32_t h0, h1, h2, h3;
                ldsm4(h0, h1, h2, h3, stg + PART_BYTES + swz(r, c16));
                #pragma unroll
                for (int mi = 0; mi < 2; mi++) {
                    mma16816(acc[mi][bj*2],   a0[mi], h0, h2);
                    mma16816(acc[mi][bj*2+1], a0[mi], h1, h3);
                }
            }
        }
    }

    const int qr = lane >> 2;
    const int qc = (lane & 3) * 2;

    if (mode == 0) {
        #pragma unroll
        for (int mi = 0; mi < 2; mi++) {
            #pragma unroll
            for (int nj = 0; nj < 8; nj++) {
                const int col = bn + n0w + nj * 8 + qc;
                const float b0 = __ldg(bias0 + col);
                const float b1 = __ldg(bias0 + col + 1);
                const int row0 = bm + m0w + mi * 16 + qr;
                *(float2*)(dstf + (size_t)row0 * CD + col) =
                    make_float2(acc[mi][nj][0] + b0, acc[mi][nj][1] + b1);
                *(float2*)(dstf + (size_t)(row0 + 8) * CD + col) =
                    make_float2(acc[mi][nj][2] + b0, acc[mi][nj][3] + b1);
            }
        }
    } else {
        // fused QKV epilogue; p uniform per CTA (GBN=128 divides 1024)
        const int p = bn >> 10;
        __half* dsth = (p == 0) ? dq : (p == 1) ? dk : dv;
        const float* bias = (p == 0) ? bias0 : (p == 1) ? bias1 : bias2;
        const float scl = (p < 2) ? invs : 1.0f;
        const int lb = bn & 1023;
        #pragma unroll
        for (int mi = 0; mi < 2; mi++) {
            #pragma unroll
            for (int nj = 0; nj < 8; nj++) {
                const int local = lb + n0w + nj * 8 + qc;
                const float b0 = __ldg(bias + local);
                const float b1 = __ldg(bias + local + 1);
                const int row0 = bm + m0w + mi * 16 + qr;
                const int h = local >> 6;
                const int d = local & 63;
                float v00 = (acc[mi][nj][0] + b0) * scl;
                float v01 = (acc[mi][nj][1] + b1) * scl;
                float v10 = (acc[mi][nj][2] + b0) * scl;
                float v11 = (acc[mi][nj][3] + b1) * scl;
                #pragma unroll
                for (int rr = 0; rr < 2; rr++) {
                    const int row = row0 + rr * 8;
                    const float x0 = rr ? v10 : v00;
                    const float x1 = rr ? v11 : v01;
                    const int bb = row >> 11;
                    const int t  = row & (CT - 1);
                    const size_t idx = ((size_t)((bb * CNH + h) * CT + t)) * 64 + d;
                    *(__half2*)(dsth + idx) = __floats2half2_rn(x0, x1);
                }
            }
        }
    }
}

// ---------------------------------------------------------------------------
// fp16 flash attention, ALiBi + causal.
// Grid: x = h*2+b (32), y = reversed tq (32)  -> longest CTAs launch first
// across ALL heads. CTA: 64 q-rows, 64-key tiles, double-buffered KV, 40KB.
// ---------------------------------------------------------------------------
#define A_QBYTES 8192
#define A_STG    16384
#define ASMEM    (A_QBYTES + 2*A_STG)   // 40KB

static __device__ __forceinline__ uint32_t swz128(int r, int c16) {
    return (uint32_t)(r * 128 + ((c16 ^ (r & 7)) << 4));
}

static __device__ __forceinline__ void a_load_kv(
    uint32_t stg, int tid,
    const __half* __restrict__ kh, const __half* __restrict__ vh, int j0)
{
    #pragma unroll
    for (int i = 0; i < 8; i++) {
        const int id = tid + i * 128;
        const int p = id >> 9;               // 0 = K, 1 = V
        const int inner = id & 511;
        const int r = inner >> 3, c = inner & 7;
        cp16(stg + (uint32_t)p * 8192 + swz128(r, c),
             (p ? vh : kh) + (size_t)(j0 + r) * 64 + c * 8);
    }
}

__global__ __launch_bounds__(128, 3)
void attn_mma(const __half* __restrict__ qh_, const __half* __restrict__ kh_,
              const __half* __restrict__ vh_, __half* __restrict__ oh)
{
    extern __shared__ char dsm[];
    const uint32_t sb = smem_u32(dsm);
    const uint32_t sqh = sb;
    const uint32_t stg0 = sb + A_QBYTES, stg1 = stg0 + A_STG;

    const int tid  = threadIdx.x;
    const int lane = tid & 31;
    const int w    = tid >> 5;
    const int hb   = blockIdx.x;               // 0..31
    const int h    = hb >> 1;
    const int b    = hb & 1;
    const int tq   = 31 - (int)blockIdx.y;     // longest first
    const int i0   = tq * 64;
    const int njt  = tq + 1;

    const size_t base = (size_t)(b * CNH + h) * CT * 64;
    const __half* qh = qh_ + base;
    const __half* kh = kh_ + base;
    const __half* vh = vh_ + base;

    const float slope = exp2f(-0.5f * (float)(h + 1));

    // Q tile load (64 rows x 128B = 512 chunks)
    #pragma unroll
    for (int i = 0; i < 4; i++) {
        const int id = tid + i * 128;
        const int r = id >> 3, c = id & 7;
        cp16(sqh + swz128(r, c), qh + (size_t)(i0 + r) * 64 + c * 8);
    }
    cp_commit();
    a_load_kv(stg0, tid, kh, vh, 0);
    cp_commit();

    cp_wait<1>();          // Q ready
    __syncthreads();

    const int lr = lane & 15;
    const int lc = lane >> 4;
    uint32_t qf[4][4];
    #pragma unroll
    for (int kk = 0; kk < 4; kk++) {
        const int r = w * 16 + lr;
        ldsm4(qf[kk][0], qf[kk][1], qf[kk][2], qf[kk][3], sqh + swz128(r, kk*2 + lc));
    }

    const int qr = lane >> 2;
    const int qc = (lane & 3) * 2;
    const int irow0 = i0 + w * 16 + qr;
    const int irow1 = irow0 + 8;

    float O[8][4];
    #pragma unroll
    for (int nj = 0; nj < 8; nj++)
        #pragma unroll
        for (int e = 0; e < 4; e++) O[nj][e] = 0.f;
    float m0 = -1e30f, m1 = -1e30f, l0 = 0.f, l1 = 0.f;

    for (int jt = 0; jt < njt; jt++) {
        if (jt + 1 < njt) {
            a_load_kv((jt & 1) ? stg0 : stg1, tid, kh, vh, (jt + 1) * 64);
            cp_commit();
            cp_wait<1>();
        } else {
            cp_wait<0>();
        }
        __syncthreads();

        const uint32_t stg = (jt & 1) ? stg1 : stg0;
        const uint32_t skh = stg, svh = stg + 8192;

        // ---- S = Q K^T ----
        float S[8][4];
        #pragma unroll
        for (int nj = 0; nj < 8; nj++)
            #pragma unroll
            for (int e = 0; e < 4; e++) S[nj][e] = 0.f;

        #pragma unroll
        for (int kk = 0; kk < 4; kk++) {
            #pragma unroll
            for (int n16 = 0; n16 < 4; n16++) {
                const int r = n16 * 16 + lr;
                uint32_t h0, h1, h2, h3;
                ldsm4(h0, h1, h2, h3, skh + swz128(r, kk*2 + lc));
                mma16816(S[n16*2],   qf[kk], h0, h2);
                mma16816(S[n16*2+1], qf[kk], h1, h3);
            }
        }

        // ---- ALiBi + causal + online softmax ----
        const int jbase = jt * 64;
        const bool lastt = (jt == njt - 1);
        float tmax0 = -1e30f, tmax1 = -1e30f;
        #pragma unroll
        for (int nj = 0; nj < 8; nj++) {
            const int j0c = jbase + nj * 8 + qc;
            #pragma unroll
            for (int e = 0; e < 4; e++) {
                const int j = j0c + (e & 1);
                const int i = (e >> 1) ? irow1 : irow0;
                float s = S[nj][e] + slope * (float)(j - i);
                if (lastt && j > i) s = -1e30f;
                S[nj][e] = s;
            }
            tmax0 = fmaxf(tmax0, fmaxf(S[nj][0], S[nj][1]));
            tmax1 = fmaxf(tmax1, fmaxf(S[nj][2], S[nj][3]));
        }
        tmax0 = fmaxf(tmax0, __shfl_xor_sync(0xFFFFFFFFu, tmax0, 1));
        tmax0 = fmaxf(tmax0, __shfl_xor_sync(0xFFFFFFFFu, tmax0, 2));
        tmax1 = fmaxf(tmax1, __shfl_xor_sync(0xFFFFFFFFu, tmax1, 1));
        tmax1 = fmaxf(tmax1, __shfl_xor_sync(0xFFFFFFFFu, tmax1, 2));

        const float mn0 = fmaxf(m0, tmax0);
        const float mn1 = fmaxf(m1, tmax1);
        const float cr0 = __expf(m0 - mn0);
        const float cr1 = __expf(m1 - mn1);
        m0 = mn0; m1 = mn1;

        float ls0 = 0.f, ls1 = 0.f;
        #pragma unroll
        for (int nj = 0; nj < 8; nj++) {
            S[nj][0] = __expf(S[nj][0] - mn0);
            S[nj][1] = __expf(S[nj][1] - mn0);
            S[nj][2] = __expf(S[nj][2] - mn1);
            S[nj][3] = __expf(S[nj][3] - mn1);
            ls0 += S[nj][0] + S[nj][1];
            ls1 += S[nj][2] + S[nj][3];
        }
        l0 = l0 * cr0 + ls0;
        l1 = l1 * cr1 + ls1;
        #pragma unroll
        for (int nj = 0; nj < 8; nj++) {
            O[nj][0] *= cr0; O[nj][1] *= cr0;
            O[nj][2] *= cr1; O[nj][3] *= cr1;
        }

        // ---- O += P V ----
        #pragma unroll
        for (int kk = 0; kk < 4; kk++) {
            uint32_t ph[4];
            {
                const float* sA = S[2*kk];
                const float* sB = S[2*kk + 1];
                __half2 t;
                t = __floats2half2_rn(sA[0], sA[1]); ph[0] = *(uint32_t*)&t;
                t = __floats2half2_rn(sA[2], sA[3]); ph[1] = *(uint32_t*)&t;
                t = __floats2half2_rn(sB[0], sB[1]); ph[2] = *(uint32_t*)&t;
                t = __floats2half2_rn(sB[2], sB[3]); ph[3] = *(uint32_t*)&t;
            }
            #pragma unroll
            for (int n16 = 0; n16 < 4; n16++) {
                const int r = kk * 16 + lr;
                uint32_t v0, v1, v2, v3;
                ldsm4t(v0, v1, v2, v3, svh + swz128(r, n16*2 + lc));
                mma16816(O[n16*2],   ph, v0, v1);
                mma16816(O[n16*2+1], ph, v2, v3);
            }
        }
        __syncthreads();
    }

    // ---- normalize + fp16 store ----
    l0 += __shfl_xor_sync(0xFFFFFFFFu, l0, 1);
    l0 += __shfl_xor_sync(0xFFFFFFFFu, l0, 2);
    l1 += __shfl_xor_sync(0xFFFFFFFFu, l1, 1);
    l1 += __shfl_xor_sync(0xFFFFFFFFu, l1, 2);
    const float inv0 = 1.0f / l0;
    const float inv1 = 1.0f / l1;

    #pragma unroll
    for (int nj = 0; nj < 8; nj++) {
        const int col = h * 64 + nj * 8 + qc;
        const size_t idx0 = (size_t)(b * CT + irow0) * CD + col;
        const size_t idx1 = (size_t)(b * CT + irow1) * CD + col;
        *(__half2*)(oh + idx0) = __floats2half2_rn(O[nj][0] * inv0, O[nj][1] * inv0);
        *(__half2*)(oh + idx1) = __floats2half2_rn(O[nj][2] * inv1, O[nj][3] * inv1);
    }
}

// ---------------------------------------------------------------------------
extern "C" void kernel_launch(void* const* d_in, const int* in_sizes, int n_in,
                              void* d_out, int out_size)
{
    (void)in_sizes; (void)n_in; (void)out_size;
    const float* x  = (const float*)d_in[0];
    const float* Wq = (const float*)d_in[1];
    const float* bq = (const float*)d_in[2];
    const float* Wk = (const float*)d_in[3];
    const float* bk = (const float*)d_in[4];
    const float* Wv = (const float*)d_in[5];
    const float* bv = (const float*)d_in[6];
    const float* Wp = (const float*)d_in[7];
    const float* bp = (const float*)d_in[8];

    __half *ah, *wh, *qh, *kh, *vh;
    cudaGetSymbolAddress((void**)&ah, g_ah);
    cudaGetSymbolAddress((void**)&wh, g_wh);
    cudaGetSymbolAddress((void**)&qh, g_qh);
    cudaGetSymbolAddress((void**)&kh, g_kh);
    cudaGetSymbolAddress((void**)&vh, g_vh);

    cudaFuncSetAttribute(tc_gemm,  cudaFuncAttributeMaxDynamicSharedMemorySize, GSMEM);
    cudaFuncSetAttribute(attn_mma, cudaFuncAttributeMaxDynamicSharedMemorySize, ASMEM);

    const int WN = CD * CD;
    const float invs = 0.17677669529663687f;   // 1024^(-0.25)

    cvt_single<<<(CM*CD/4 + 255)/256, 256>>>(x, ah, CM*CD/4);
    cvt_w4<<<(4*W_N4 + 255)/256, 256>>>(Wq, Wk, Wv, Wp, wh);

    // Fused QKV projection: C[4096, 3072] vs stacked Wq|Wk|Wv
    tc_gemm<<<dim3(3*CD / GBN, CM / GBM), 256, GSMEM>>>(
        ah, wh, bq, bk, bv, nullptr, qh, kh, vh, invs, 1);

    attn_mma<<<dim3(2*CNH, CT/64), 128, ASMEM>>>(qh, kh, vh, ah);

    // Output projection
    tc_gemm<<<dim3(CD / GBN, CM / GBM), 256, GSMEM>>>(
        ah, wh + 3*WN, bp, nullptr, nullptr, (float*)d_out,
        nullptr, nullptr, nullptr, 1.0f, 0);
}

// round 11
// speedup vs baseline: 2.7360x; 1.0775x over previous
#include <cuda_runtime.h>
#include <cuda_fp16.h>
#include <cstdint>

// Problem constants
#define CB 2
#define CT 2048
#define CD 1024
#define CNH 16
#define CHD 64
#define CM (CB*CT)              // 4096 rows

#define LOG2E 1.4426950408889634f

// ---------------------------------------------------------------------------
// Scratch (device globals)
// ---------------------------------------------------------------------------
__device__ __half g_ah[CM*CD];          // A operand (x, then att out)
__device__ __half g_wh[4*CD*CD];        // Wq|Wk|Wv|Wp stacked, fp16
__device__ __half g_qh[CM*CD];          // head-major [B,NH,T,64]; Q pre-scaled by log2e
__device__ __half g_kh[CM*CD];
__device__ __half g_vh[CM*CD];

// ---------------------------------------------------------------------------
// PTX helpers
// ---------------------------------------------------------------------------
static __device__ __forceinline__ void cp16(uint32_t d, const void* s) {
    asm volatile("cp.async.cg.shared.global [%0], [%1], 16;\n" :: "r"(d), "l"(s));
}
static __device__ __forceinline__ void cp_commit() {
    asm volatile("cp.async.commit_group;\n" ::: "memory");
}
template<int N> static __device__ __forceinline__ void cp_wait() {
    asm volatile("cp.async.wait_group %0;\n" :: "n"(N) : "memory");
}
static __device__ __forceinline__ void ldsm4(uint32_t& r0, uint32_t& r1,
                                             uint32_t& r2, uint32_t& r3, uint32_t a) {
    asm volatile("ldmatrix.sync.aligned.m8n8.x4.shared.b16 {%0,%1,%2,%3}, [%4];"
                 : "=r"(r0), "=r"(r1), "=r"(r2), "=r"(r3) : "r"(a));
}
static __device__ __forceinline__ void ldsm4t(uint32_t& r0, uint32_t& r1,
                                              uint32_t& r2, uint32_t& r3, uint32_t a) {
    asm volatile("ldmatrix.sync.aligned.m8n8.x4.trans.shared.b16 {%0,%1,%2,%3}, [%4];"
                 : "=r"(r0), "=r"(r1), "=r"(r2), "=r"(r3) : "r"(a));
}
static __device__ __forceinline__ void mma16816(float* c, const uint32_t* a,
                                                uint32_t b0, uint32_t b1) {
    asm volatile(
        "mma.sync.aligned.m16n8k16.row.col.f32.f16.f16.f32 "
        "{%0,%1,%2,%3}, {%4,%5,%6,%7}, {%8,%9}, {%0,%1,%2,%3};"
        : "+f"(c[0]), "+f"(c[1]), "+f"(c[2]), "+f"(c[3])
        : "r"(a[0]), "r"(a[1]), "r"(a[2]), "r"(a[3]), "r"(b0), "r"(b1));
}
static __device__ __forceinline__ uint32_t smem_u32(const void* p) {
    uint32_t r;
    asm("{ .reg .u64 t; cvta.to.shared.u64 t, %1; cvt.u32.u64 %0, t; }" : "=r"(r) : "l"(p));
    return r;
}

// ---------------------------------------------------------------------------
// fp32 -> fp16 conversions
// ---------------------------------------------------------------------------
__global__ __launch_bounds__(256)
void cvt_single(const float* __restrict__ s, __half* __restrict__ d, int n4)
{
    int i = blockIdx.x * blockDim.x + threadIdx.x;
    if (i >= n4) return;
    float4 v = ((const float4*)s)[i];
    ((__half2*)d)[2*i]   = __floats2half2_rn(v.x, v.y);
    ((__half2*)d)[2*i+1] = __floats2half2_rn(v.z, v.w);
}

#define W_N4 (CD*CD/4)
__global__ __launch_bounds__(256)
void cvt_w4(const float* __restrict__ s0, const float* __restrict__ s1,
            const float* __restrict__ s2, const float* __restrict__ s3,
            __half* __restrict__ d)
{
    int i = blockIdx.x * blockDim.x + threadIdx.x;
    if (i >= 4 * W_N4) return;
    const int p = i >> 18;
    const int j = i & (W_N4 - 1);
    const float* s = (p == 0) ? s0 : (p == 1) ? s1 : (p == 2) ? s2 : s3;
    float4 v = ((const float4*)s)[j];
    ((__half2*)d)[2*i]   = __floats2half2_rn(v.x, v.y);
    ((__half2*)d)[2*i+1] = __floats2half2_rn(v.z, v.w);
}

// ---------------------------------------------------------------------------
// mma.sync fp16 GEMM: C = A @ B^T.
// mode 0: out = C+bias0 fp32 row-major [CM,CD]  (output projection)
// mode 1: fused QKV (N=3072): p=bn>>10 -> {q,k,v}; q scaled by invs*log2e,
//         k by invs, v by 1.  fp16 head-major out.
// ---------------------------------------------------------------------------
#define GBM 128
#define GBN 128
#define GBK 32
#define GSTAGES 4
#define GNKT (CD/GBK)
#define PART_BYTES 8192
#define STG_BYTES (2*PART_BYTES)
#define GSMEM (GSTAGES*STG_BYTES)      // 64KB

static __device__ __forceinline__ uint32_t swz(int r, int c16) {
    return (uint32_t)(r * 64 + ((c16 ^ ((r >> 1) & 3)) << 4));
}

static __device__ __forceinline__ void g_load_stage(
    uint32_t sbase, int kt, int tid,
    const __half* __restrict__ Ah, const __half* __restrict__ Bh,
    int bm, int bn)
{
    const int k0 = kt * GBK;
    #pragma unroll
    for (int i = 0; i < 4; i++) {
        const int id = tid + i * 256;
        const int p = id >> 9;
        const int inner = id & 511;
        const int r = inner >> 2;
        const int c = inner & 3;
        const int rowbase = p ? bn : bm;
        cp16(sbase + (uint32_t)p * PART_BYTES + swz(r, c),
             (p ? Bh : Ah) + (size_t)(rowbase + r) * CD + k0 + c * 8);
    }
}

__global__ __launch_bounds__(256, 2)
void tc_gemm(const __half* __restrict__ Ah, const __half* __restrict__ Bh,
             const float* __restrict__ bias0, const float* __restrict__ bias1,
             const float* __restrict__ bias2,
             float* __restrict__ dstf,
             __half* __restrict__ dq, __half* __restrict__ dk,
             __half* __restrict__ dv,
             float invs, int mode)
{
    extern __shared__ char dsm[];
    uint32_t sb = smem_u32(dsm);

    const int tid  = threadIdx.x;
    const int wid  = tid >> 5;
    const int lane = tid & 31;
    const int bm   = blockIdx.y * GBM;
    const int bn   = blockIdx.x * GBN;
    const int m0w  = (wid & 3) * 32;
    const int n0w  = (wid >> 2) * 64;

    float acc[2][8][4];
    #pragma unroll
    for (int i = 0; i < 2; i++)
        #pragma unroll
        for (int j = 0; j < 8; j++)
            #pragma unroll
            for (int k = 0; k < 4; k++) acc[i][j][k] = 0.f;

    #pragma unroll
    for (int s = 0; s < GSTAGES - 1; s++) {
        g_load_stage(sb + s * STG_BYTES, s, tid, Ah, Bh, bm, bn);
        cp_commit();
    }

    const int lr = lane & 15;
    const int lc = lane >> 4;

    for (int kt = 0; kt < GNKT; kt++) {
        cp_wait<GSTAGES - 2>();
        __syncthreads();

        if (kt + GSTAGES - 1 < GNKT) {
            g_load_stage(sb + ((kt + GSTAGES - 1) % GSTAGES) * STG_BYTES,
                         kt + GSTAGES - 1, tid, Ah, Bh, bm, bn);
        }
        cp_commit();

        const uint32_t stg = sb + (uint32_t)(kt % GSTAGES) * STG_BYTES;
        #pragma unroll
        for (int ks = 0; ks < 2; ks++) {
            const int c16 = 2 * ks + lc;
            uint32_t a0[2][4];
            #pragma unroll
            for (int mi = 0; mi < 2; mi++) {
                const int r = m0w + mi * 16 + lr;
                ldsm4(a0[mi][0], a0[mi][1], a0[mi][2], a0[mi][3],
                      stg + swz(r, c16));
            }
            #pragma unroll
            for (int bj = 0; bj < 4; bj++) {
                const int r = n0w + bj * 16 + lr;
                uint32_t h0, h1, h2, h3;
                ldsm4(h0, h1, h2, h3, stg + PART_BYTES + swz(r, c16));
                #pragma unroll
                for (int mi = 0; mi < 2; mi++) {
                    mma16816(acc[mi][bj*2],   a0[mi], h0, h2);
                    mma16816(acc[mi][bj*2+1], a0[mi], h1, h3);
                }
            }
        }
    }

    const int qr = lane >> 2;
    const int qc = (lane & 3) * 2;

    if (mode == 0) {
        #pragma unroll
        for (int mi = 0; mi < 2; mi++) {
            #pragma unroll
            for (int nj = 0; nj < 8; nj++) {
                const int col = bn + n0w + nj * 8 + qc;
                const float b0 = __ldg(bias0 + col);
                const float b1 = __ldg(bias0 + col + 1);
                const int row0 = bm + m0w + mi * 16 + qr;
                *(float2*)(dstf + (size_t)row0 * CD + col) =
                    make_float2(acc[mi][nj][0] + b0, acc[mi][nj][1] + b1);
                *(float2*)(dstf + (size_t)(row0 + 8) * CD + col) =
                    make_float2(acc[mi][nj][2] + b0, acc[mi][nj][3] + b1);
            }
        }
    } else {
        const int p = bn >> 10;
        __half* dsth = (p == 0) ? dq : (p == 1) ? dk : dv;
        const float* bias = (p == 0) ? bias0 : (p == 1) ? bias1 : bias2;
        const float scl = (p == 0) ? invs * LOG2E : (p == 1) ? invs : 1.0f;
        const int lb = bn & 1023;
        #pragma unroll
        for (int mi = 0; mi < 2; mi++) {
            #pragma unroll
            for (int nj = 0; nj < 8; nj++) {
                const int local = lb + n0w + nj * 8 + qc;
                const float b0 = __ldg(bias + local);
                const float b1 = __ldg(bias + local + 1);
                const int row0 = bm + m0w + mi * 16 + qr;
                const int h = local >> 6;
                const int d = local & 63;
                float v00 = (acc[mi][nj][0] + b0) * scl;
                float v01 = (acc[mi][nj][1] + b1) * scl;
                float v10 = (acc[mi][nj][2] + b0) * scl;
                float v11 = (acc[mi][nj][3] + b1) * scl;
                #pragma unroll
                for (int rr = 0; rr < 2; rr++) {
                    const int row = row0 + rr * 8;
                    const float x0 = rr ? v10 : v00;
                    const float x1 = rr ? v11 : v01;
                    const int bb = row >> 11;
                    const int t  = row & (CT - 1);
                    const size_t idx = ((size_t)((bb * CNH + h) * CT + t)) * 64 + d;
                    *(__half2*)(dsth + idx) = __floats2half2_rn(x0, x1);
                }
            }
        }
    }
}

// ---------------------------------------------------------------------------
// fp16 flash attention, ALiBi + causal, STATIC-MAX log2-domain softmax.
// P = exp2( S + slope2*(j - i) - LOG2E )  with S = (Q*log2e)·K from mma.
// Softmax row-invariance makes this exactly equal to the max-tracked version;
// scores are bounded so fp32 cannot overflow; far-past terms underflow to 0.
// ---------------------------------------------------------------------------
#define A_QBYTES 8192
#define A_STG    16384
#define ASMEM    (A_QBYTES + 2*A_STG)   // 40KB

static __device__ __forceinline__ uint32_t swz128(int r, int c16) {
    return (uint32_t)(r * 128 + ((c16 ^ (r & 7)) << 4));
}

static __device__ __forceinline__ void a_load_kv(
    uint32_t stg, int tid,
    const __half* __restrict__ kh, const __half* __restrict__ vh, int j0)
{
    #pragma unroll
    for (int i = 0; i < 8; i++) {
        const int id = tid + i * 128;
        const int p = id >> 9;               // 0 = K, 1 = V
        const int inner = id & 511;
        const int r = inner >> 3, c = inner & 7;
        cp16(stg + (uint32_t)p * 8192 + swz128(r, c),
             (p ? vh : kh) + (size_t)(j0 + r) * 64 + c * 8);
    }
}

__global__ __launch_bounds__(128, 3)
void attn_mma(const __half* __restrict__ qh_, const __half* __restrict__ kh_,
              const __half* __restrict__ vh_, __half* __restrict__ oh)
{
    extern __shared__ char dsm[];
    const uint32_t sb = smem_u32(dsm);
    const uint32_t sqh = sb;
    const uint32_t stg0 = sb + A_QBYTES, stg1 = stg0 + A_STG;

    const int tid  = threadIdx.x;
    const int lane = tid & 31;
    const int w    = tid >> 5;
    const int hb   = blockIdx.x;               // 0..31
    const int h    = hb >> 1;
    const int b    = hb & 1;
    const int tq   = 31 - (int)blockIdx.y;     // longest first
    const int i0   = tq * 64;
    const int njt  = tq + 1;

    const size_t base = (size_t)(b * CNH + h) * CT * 64;
    const __half* qh = qh_ + base;
    const __half* kh = kh_ + base;
    const __half* vh = vh_ + base;

    const float slope2 = exp2f(-0.5f * (float)(h + 1)) * LOG2E;

    // Q tile load
    #pragma unroll
    for (int i = 0; i < 4; i++) {
        const int id = tid + i * 128;
        const int r = id >> 3, c = id & 7;
        cp16(sqh + swz128(r, c), qh + (size_t)(i0 + r) * 64 + c * 8);
    }
    cp_commit();
    a_load_kv(stg0, tid, kh, vh, 0);
    cp_commit();

    cp_wait<1>();
    __syncthreads();

    const int lr = lane & 15;
    const int lc = lane >> 4;
    uint32_t qf[4][4];
    #pragma unroll
    for (int kk = 0; kk < 4; kk++) {
        const int r = w * 16 + lr;
        ldsm4(qf[kk][0], qf[kk][1], qf[kk][2], qf[kk][3], sqh + swz128(r, kk*2 + lc));
    }

    const int qr = lane >> 2;
    const int qc = (lane & 3) * 2;
    const int irow0 = i0 + w * 16 + qr;
    const int irow1 = irow0 + 8;

    // ALiBi per-column constants (within a tile): slope2*(nj*8 + qc + parity)
    float cnj0[8], cnj1[8];
    #pragma unroll
    for (int nj = 0; nj < 8; nj++) {
        cnj0[nj] = slope2 * (float)(nj * 8 + qc);
        cnj1[nj] = cnj0[nj] + slope2;
    }
    // per-row bases (j-part added per tile): slope2*(jbase - i) - LOG2E
    const float rb0 = -slope2 * (float)irow0 - LOG2E;
    const float rb1 = -slope2 * (float)irow1 - LOG2E;

    float O[8][4];
    #pragma unroll
    for (int nj = 0; nj < 8; nj++)
        #pragma unroll
        for (int e = 0; e < 4; e++) O[nj][e] = 0.f;
    float l0 = 0.f, l1 = 0.f;

    for (int jt = 0; jt < njt; jt++) {
        if (jt + 1 < njt) {
            a_load_kv((jt & 1) ? stg0 : stg1, tid, kh, vh, (jt + 1) * 64);
            cp_commit();
            cp_wait<1>();
        } else {
            cp_wait<0>();
        }
        __syncthreads();

        const uint32_t stg = (jt & 1) ? stg1 : stg0;
        const uint32_t skh = stg, svh = stg + 8192;

        // ---- S initialized with ALiBi bias, then += Q K^T via mma ----
        const float jb = slope2 * (float)(jt * 64);
        const float b0r = jb + rb0;
        const float b1r = jb + rb1;
        float S[8][4];
        #pragma unroll
        for (int nj = 0; nj < 8; nj++) {
            S[nj][0] = b0r + cnj0[nj];
            S[nj][1] = b0r + cnj1[nj];
            S[nj][2] = b1r + cnj0[nj];
            S[nj][3] = b1r + cnj1[nj];
        }

        #pragma unroll
        for (int kk = 0; kk < 4; kk++) {
            #pragma unroll
            for (int n16 = 0; n16 < 4; n16++) {
                const int r = n16 * 16 + lr;
                uint32_t h0, h1, h2, h3;
                ldsm4(h0, h1, h2, h3, skh + swz128(r, kk*2 + lc));
                mma16816(S[n16*2],   qf[kk], h0, h2);
                mma16816(S[n16*2+1], qf[kk], h1, h3);
            }
        }

        // ---- P = exp2(S); causal zeroing only in the diagonal tile ----
        #pragma unroll
        for (int nj = 0; nj < 8; nj++) {
            S[nj][0] = exp2f(S[nj][0]);
            S[nj][1] = exp2f(S[nj][1]);
            S[nj][2] = exp2f(S[nj][2]);
            S[nj][3] = exp2f(S[nj][3]);
        }
        if (jt == njt - 1) {
            const int jbase = jt * 64;
            #pragma unroll
            for (int nj = 0; nj < 8; nj++) {
                const int j0c = jbase + nj * 8 + qc;
                if (j0c > irow0)     S[nj][0] = 0.f;
                if (j0c + 1 > irow0) S[nj][1] = 0.f;
                if (j0c > irow1)     S[nj][2] = 0.f;
                if (j0c + 1 > irow1) S[nj][3] = 0.f;
            }
        }
        #pragma unroll
        for (int nj = 0; nj < 8; nj++) {
            l0 += S[nj][0] + S[nj][1];
            l1 += S[nj][2] + S[nj][3];
        }

        // ---- O += P V ----
        #pragma unroll
        for (int kk = 0; kk < 4; kk++) {
            uint32_t ph[4];
            {
                const float* sA = S[2*kk];
                const float* sB = S[2*kk + 1];
                __half2 t;
                t = __floats2half2_rn(sA[0], sA[1]); ph[0] = *(uint32_t*)&t;
                t = __floats2half2_rn(sA[2], sA[3]); ph[1] = *(uint32_t*)&t;
                t = __floats2half2_rn(sB[0], sB[1]); ph[2] = *(uint32_t*)&t;
                t = __floats2half2_rn(sB[2], sB[3]); ph[3] = *(uint32_t*)&t;
            }
            #pragma unroll
            for (int n16 = 0; n16 < 4; n16++) {
                const int r = kk * 16 + lr;
                uint32_t v0, v1, v2, v3;
                ldsm4t(v0, v1, v2, v3, svh + swz128(r, n16*2 + lc));
                mma16816(O[n16*2],   ph, v0, v1);
                mma16816(O[n16*2+1], ph, v2, v3);
            }
        }
        __syncthreads();
    }

    // ---- final l reduction + normalize + fp16 store ----
    l0 += __shfl_xor_sync(0xFFFFFFFFu, l0, 1);
    l0 += __shfl_xor_sync(0xFFFFFFFFu, l0, 2);
    l1 += __shfl_xor_sync(0xFFFFFFFFu, l1, 1);
    l1 += __shfl_xor_sync(0xFFFFFFFFu, l1, 2);
    const float inv0 = 1.0f / l0;
    const float inv1 = 1.0f / l1;

    #pragma unroll
    for (int nj = 0; nj < 8; nj++) {
        const int col = h * 64 + nj * 8 + qc;
        const size_t idx0 = (size_t)(b * CT + irow0) * CD + col;
        const size_t idx1 = (size_t)(b * CT + irow1) * CD + col;
        *(__half2*)(oh + idx0) = __floats2half2_rn(O[nj][0] * inv0, O[nj][1] * inv0);
        *(__half2*)(oh + idx1) = __floats2half2_rn(O[nj][2] * inv1, O[nj][3] * inv1);
    }
}

// ---------------------------------------------------------------------------
extern "C" void kernel_launch(void* const* d_in, const int* in_sizes, int n_in,
                              void* d_out, int out_size)
{
    (void)in_sizes; (void)n_in; (void)out_size;
    const float* x  = (const float*)d_in[0];
    const float* Wq = (const float*)d_in[1];
    const float* bq = (const float*)d_in[2];
    const float* Wk = (const float*)d_in[3];
    const float* bk = (const float*)d_in[4];
    const float* Wv = (const float*)d_in[5];
    const float* bv = (const float*)d_in[6];
    const float* Wp = (const float*)d_in[7];
    const float* bp = (const float*)d_in[8];

    __half *ah, *wh, *qh, *kh, *vh;
    cudaGetSymbolAddress((void**)&ah, g_ah);
    cudaGetSymbolAddress((void**)&wh, g_wh);
    cudaGetSymbolAddress((void**)&qh, g_qh);
    cudaGetSymbolAddress((void**)&kh, g_kh);
    cudaGetSymbolAddress((void**)&vh, g_vh);

    cudaFuncSetAttribute(tc_gemm,  cudaFuncAttributeMaxDynamicSharedMemorySize, GSMEM);
    cudaFuncSetAttribute(attn_mma, cudaFuncAttributeMaxDynamicSharedMemorySize, ASMEM);

    const int WN = CD * CD;
    const float invs = 0.17677669529663687f;   // 1024^(-0.25)

    cvt_single<<<(CM*CD/4 + 255)/256, 256>>>(x, ah, CM*CD/4);
    cvt_w4<<<(4*W_N4 + 255)/256, 256>>>(Wq, Wk, Wv, Wp, wh);

    tc_gemm<<<dim3(3*CD / GBN, CM / GBM), 256, GSMEM>>>(
        ah, wh, bq, bk, bv, nullptr, qh, kh, vh, invs, 1);

    attn_mma<<<dim3(2*CNH, CT/64), 128, ASMEM>>>(qh, kh, vh, ah);

    tc_gemm<<<dim3(CD / GBN, CM / GBM), 256, GSMEM>>>(
        ah, wh + 3*WN, bp, nullptr, nullptr, (float*)d_out,
        nullptr, nullptr, nullptr, 1.0f, 0);
}

// round 13
// speedup vs baseline: 2.9985x; 1.0959x over previous
#include <cuda_runtime.h>
#include <cuda_fp16.h>
#include <cstdint>

// Problem constants
#define CB 2
#define CT 2048
#define CD 1024
#define CNH 16
#define CHD 64
#define CM (CB*CT)              // 4096 rows

#define LOG2E 1.4426950408889634f

// ---------------------------------------------------------------------------
// Scratch (device globals)
// ---------------------------------------------------------------------------
__device__ __half g_ah[CM*CD];          // A operand (x, then att out)
__device__ __half g_wh[4*CD*CD];        // Wq|Wk|Wv|Wp stacked, fp16
__device__ __half g_qh[CM*CD];          // head-major [B,NH,T,64]; Q pre-scaled by log2e
__device__ __half g_kh[CM*CD];
__device__ __half g_vh[CM*CD];

// ---------------------------------------------------------------------------
// PTX helpers
// ---------------------------------------------------------------------------
static __device__ __forceinline__ void cp16(uint32_t d, const void* s) {
    asm volatile("cp.async.cg.shared.global [%0], [%1], 16;\n" :: "r"(d), "l"(s));
}
static __device__ __forceinline__ void cp_commit() {
    asm volatile("cp.async.commit_group;\n" ::: "memory");
}
template<int N> static __device__ __forceinline__ void cp_wait() {
    asm volatile("cp.async.wait_group %0;\n" :: "n"(N) : "memory");
}
static __device__ __forceinline__ void ldsm4(uint32_t& r0, uint32_t& r1,
                                             uint32_t& r2, uint32_t& r3, uint32_t a) {
    asm volatile("ldmatrix.sync.aligned.m8n8.x4.shared.b16 {%0,%1,%2,%3}, [%4];"
                 : "=r"(r0), "=r"(r1), "=r"(r2), "=r"(r3) : "r"(a));
}
static __device__ __forceinline__ void ldsm4t(uint32_t& r0, uint32_t& r1,
                                              uint32_t& r2, uint32_t& r3, uint32_t a) {
    asm volatile("ldmatrix.sync.aligned.m8n8.x4.trans.shared.b16 {%0,%1,%2,%3}, [%4];"
                 : "=r"(r0), "=r"(r1), "=r"(r2), "=r"(r3) : "r"(a));
}
static __device__ __forceinline__ void mma16816(float* c, const uint32_t* a,
                                                uint32_t b0, uint32_t b1) {
    asm volatile(
        "mma.sync.aligned.m16n8k16.row.col.f32.f16.f16.f32 "
        "{%0,%1,%2,%3}, {%4,%5,%6,%7}, {%8,%9}, {%0,%1,%2,%3};"
        : "+f"(c[0]), "+f"(c[1]), "+f"(c[2]), "+f"(c[3])
        : "r"(a[0]), "r"(a[1]), "r"(a[2]), "r"(a[3]), "r"(b0), "r"(b1));
}
static __device__ __forceinline__ uint32_t smem_u32(const void* p) {
    uint32_t r;
    asm("{ .reg .u64 t; cvta.to.shared.u64 t, %1; cvt.u32.u64 %0, t; }" : "=r"(r) : "l"(p));
    return r;
}

// 128B-row swizzle (shared by GEMM and attention tiles)
static __device__ __forceinline__ uint32_t swz128(int r, int c16) {
    return (uint32_t)(r * 128 + ((c16 ^ (r & 7)) << 4));
}

// ---------------------------------------------------------------------------
// Fused fp32 -> fp16 conversion: x (1M float4) + 4 weights (1M float4), 1 launch
// ---------------------------------------------------------------------------
#define X_N4 (CM*CD/4)                 // 1048576
#define W_N4 (CD*CD/4)                 // 262144
__global__ __launch_bounds__(256)
void cvt_all(const float* __restrict__ x,
             const float* __restrict__ w0, const float* __restrict__ w1,
             const float* __restrict__ w2, const float* __restrict__ w3,
             __half* __restrict__ dx, __half* __restrict__ dw)
{
    int i = blockIdx.x * blockDim.x + threadIdx.x;
    if (i >= X_N4 + 4 * W_N4) return;
    const float* s;
    __half* d;
    int j;
    if (i < X_N4) {
        s = x; d = dx; j = i;
    } else {
        const int k = i - X_N4;
        const int p = k >> 18;
        j = k & (W_N4 - 1);
        s = (p == 0) ? w0 : (p == 1) ? w1 : (p == 2) ? w2 : w3;
        d = dw + (size_t)p * (CD*CD);
    }
    float4 v = ((const float4*)s)[j];
    ((__half2*)d)[2*j]   = __floats2half2_rn(v.x, v.y);
    ((__half2*)d)[2*j+1] = __floats2half2_rn(v.z, v.w);
}

// ---------------------------------------------------------------------------
// mma.sync fp16 GEMM: C = A @ B^T.
// Stage = BK 64: A 16KB | B 16KB = 32KB; 3 stages = 96KB, 2 CTAs/SM;
// one __syncthreads per 64-deep k-step (16 total vs 32 before).
// mode 0: out = C+bias0 fp32 row-major [CM,CD]
// mode 1: fused QKV (N=3072): p=bn>>10 -> {q,k,v}; q scaled by invs*log2e.
// ---------------------------------------------------------------------------
#define GBM 128
#define GBN 128
#define GBK 64
#define GSTAGES 3
#define GNKT (CD/GBK)                  // 16
#define PARTB 16384                    // bytes per operand per stage (128 x 128B)
#define STG_BYTES (2*PARTB)            // 32KB
#define GSMEM (GSTAGES*STG_BYTES)      // 96KB

static __device__ __forceinline__ void g_load_stage(
    uint32_t sbase, int kt, int tid,
    const __half* __restrict__ Ah, const __half* __restrict__ Bh,
    int bm, int bn)
{
    const int k0 = kt * GBK;
    #pragma unroll
    for (int i = 0; i < 8; i++) {
        const int id = tid + i * 256;          // 0..2047
        const int p = id >> 10;                // 0 = A, 1 = B
        const int inner = id & 1023;
        const int r = inner >> 3;
        const int c = inner & 7;
        const int rowbase = p ? bn : bm;
        cp16(sbase + (uint32_t)p * PARTB + swz128(r, c),
             (p ? Bh : Ah) + (size_t)(rowbase + r) * CD + k0 + c * 8);
    }
}

__global__ __launch_bounds__(256, 2)
void tc_gemm(const __half* __restrict__ Ah, const __half* __restrict__ Bh,
             const float* __restrict__ bias0, const float* __restrict__ bias1,
             const float* __restrict__ bias2,
             float* __restrict__ dstf,
             __half* __restrict__ dq, __half* __restrict__ dk,
             __half* __restrict__ dv,
             float invs, int mode)
{
    extern __shared__ char dsm[];
    uint32_t sb = smem_u32(dsm);

    const int tid  = threadIdx.x;
    const int wid  = tid >> 5;
    const int lane = tid & 31;
    const int bm   = blockIdx.y * GBM;
    const int bn   = blockIdx.x * GBN;
    const int m0w  = (wid & 3) * 32;
    const int n0w  = (wid >> 2) * 64;

    float acc[2][8][4];
    #pragma unroll
    for (int i = 0; i < 2; i++)
        #pragma unroll
        for (int j = 0; j < 8; j++)
            #pragma unroll
            for (int k = 0; k < 4; k++) acc[i][j][k] = 0.f;

    #pragma unroll
    for (int s = 0; s < GSTAGES - 1; s++) {
        g_load_stage(sb + s * STG_BYTES, s, tid, Ah, Bh, bm, bn);
        cp_commit();
    }

    const int lr = lane & 15;
    const int lc = lane >> 4;

    for (int kt = 0; kt < GNKT; kt++) {
        cp_wait<GSTAGES - 2>();
        __syncthreads();

        if (kt + GSTAGES - 1 < GNKT) {
            g_load_stage(sb + ((kt + GSTAGES - 1) % GSTAGES) * STG_BYTES,
                         kt + GSTAGES - 1, tid, Ah, Bh, bm, bn);
        }
        cp_commit();

        const uint32_t stg = sb + (uint32_t)(kt % GSTAGES) * STG_BYTES;
        #pragma unroll
        for (int ks = 0; ks < 4; ks++) {          // 4 k16 chunks in BK=64
            const int c16 = 2 * ks + lc;
            uint32_t a0[2][4];
            #pragma unroll
            for (int mi = 0; mi < 2; mi++) {
                const int r = m0w + mi * 16 + lr;
                ldsm4(a0[mi][0], a0[mi][1], a0[mi][2], a0[mi][3],
                      stg + swz128(r, c16));
            }
            #pragma unroll
            for (int bj = 0; bj < 4; bj++) {
                const int r = n0w + bj * 16 + lr;
                uint32_t h0, h1, h2, h3;
                ldsm4(h0, h1, h2, h3, stg + PARTB + swz128(r, c16));
                #pragma unroll
                for (int mi = 0; mi < 2; mi++) {
                    mma16816(acc[mi][bj*2],   a0[mi], h0, h2);
                    mma16816(acc[mi][bj*2+1], a0[mi], h1, h3);
                }
            }
        }
    }

    const int qr = lane >> 2;
    const int qc = (lane & 3) * 2;

    if (mode == 0) {
        #pragma unroll
        for (int mi = 0; mi < 2; mi++) {
            #pragma unroll
            for (int nj = 0; nj < 8; nj++) {
                const int col = bn + n0w + nj * 8 + qc;
                const float b0 = __ldg(bias0 + col);
                const float b1 = __ldg(bias0 + col + 1);
                const int row0 = bm + m0w + mi * 16 + qr;
                *(float2*)(dstf + (size_t)row0 * CD + col) =
                    make_float2(acc[mi][nj][0] + b0, acc[mi][nj][1] + b1);
                *(float2*)(dstf + (size_t)(row0 + 8) * CD + col) =
                    make_float2(acc[mi][nj][2] + b0, acc[mi][nj][3] + b1);
            }
        }
    } else {
        const int p = bn >> 10;
        __half* dsth = (p == 0) ? dq : (p == 1) ? dk : dv;
        const float* bias = (p == 0) ? bias0 : (p == 1) ? bias1 : bias2;
        const float scl = (p == 0) ? invs * LOG2E : (p == 1) ? invs : 1.0f;
        const int lb = bn & 1023;
        #pragma unroll
        for (int mi = 0; mi < 2; mi++) {
            #pragma unroll
            for (int nj = 0; nj < 8; nj++) {
                const int local = lb + n0w + nj * 8 + qc;
                const float b0 = __ldg(bias + local);
                const float b1 = __ldg(bias + local + 1);
                const int row0 = bm + m0w + mi * 16 + qr;
                const int h = local >> 6;
                const int d = local & 63;
                float v00 = (acc[mi][nj][0] + b0) * scl;
                float v01 = (acc[mi][nj][1] + b1) * scl;
                float v10 = (acc[mi][nj][2] + b0) * scl;
                float v11 = (acc[mi][nj][3] + b1) * scl;
                #pragma unroll
                for (int rr = 0; rr < 2; rr++) {
                    const int row = row0 + rr * 8;
                    const float x0 = rr ? v10 : v00;
                    const float x1 = rr ? v11 : v01;
                    const int bb = row >> 11;
                    const int t  = row & (CT - 1);
                    const size_t idx = ((size_t)((bb * CNH + h) * CT + t)) * 64 + d;
                    *(__half2*)(dsth + idx) = __floats2half2_rn(x0, x1);
                }
            }
        }
    }
}

// ---------------------------------------------------------------------------
// fp16 flash attention, ALiBi + causal, static-max log2-domain softmax.
// (unchanged from R11 — at its pipe floor)
// ---------------------------------------------------------------------------
#define A_QBYTES 8192
#define A_STG    16384
#define ASMEM    (A_QBYTES + 2*A_STG)   // 40KB

static __device__ __forceinline__ void a_load_kv(
    uint32_t stg, int tid,
    const __half* __restrict__ kh, const __half* __restrict__ vh, int j0)
{
    #pragma unroll
    for (int i = 0; i < 8; i++) {
        const int id = tid + i * 128;
        const int p = id >> 9;               // 0 = K, 1 = V
        const int inner = id & 511;
        const int r = inner >> 3, c = inner & 7;
        cp16(stg + (uint32_t)p * 8192 + swz128(r, c),
             (p ? vh : kh) + (size_t)(j0 + r) * 64 + c * 8);
    }
}

__global__ __launch_bounds__(128, 3)
void attn_mma(const __half* __restrict__ qh_, const __half* __restrict__ kh_,
              const __half* __restrict__ vh_, __half* __restrict__ oh)
{
    extern __shared__ char dsm[];
    const uint32_t sb = smem_u32(dsm);
    const uint32_t sqh = sb;
    const uint32_t stg0 = sb + A_QBYTES, stg1 = stg0 + A_STG;

    const int tid  = threadIdx.x;
    const int lane = tid & 31;
    const int w    = tid >> 5;
    const int hb   = blockIdx.x;               // 0..31
    const int h    = hb >> 1;
    const int b    = hb & 1;
    const int tq   = 31 - (int)blockIdx.y;     // longest first
    const int i0   = tq * 64;
    const int njt  = tq + 1;

    const size_t base = (size_t)(b * CNH + h) * CT * 64;
    const __half* qh = qh_ + base;
    const __half* kh = kh_ + base;
    const __half* vh = vh_ + base;

    const float slope2 = exp2f(-0.5f * (float)(h + 1)) * LOG2E;

    // Q tile load
    #pragma unroll
    for (int i = 0; i < 4; i++) {
        const int id = tid + i * 128;
        const int r = id >> 3, c = id & 7;
        cp16(sqh + swz128(r, c), qh + (size_t)(i0 + r) * 64 + c * 8);
    }
    cp_commit();
    a_load_kv(stg0, tid, kh, vh, 0);
    cp_commit();

    cp_wait<1>();
    __syncthreads();

    const int lr = lane & 15;
    const int lc = lane >> 4;
    uint32_t qf[4][4];
    #pragma unroll
    for (int kk = 0; kk < 4; kk++) {
        const int r = w * 16 + lr;
        ldsm4(qf[kk][0], qf[kk][1], qf[kk][2], qf[kk][3], sqh + swz128(r, kk*2 + lc));
    }

    const int qr = lane >> 2;
    const int qc = (lane & 3) * 2;
    const int irow0 = i0 + w * 16 + qr;
    const int irow1 = irow0 + 8;

    float cnj0[8], cnj1[8];
    #pragma unroll
    for (int nj = 0; nj < 8; nj++) {
        cnj0[nj] = slope2 * (float)(nj * 8 + qc);
        cnj1[nj] = cnj0[nj] + slope2;
    }
    const float rb0 = -slope2 * (float)irow0 - LOG2E;
    const float rb1 = -slope2 * (float)irow1 - LOG2E;

    float O[8][4];
    #pragma unroll
    for (int nj = 0; nj < 8; nj++)
        #pragma unroll
        for (int e = 0; e < 4; e++) O[nj][e] = 0.f;
    float l0 = 0.f, l1 = 0.f;

    for (int jt = 0; jt < njt; jt++) {
        if (jt + 1 < njt) {
            a_load_kv((jt & 1) ? stg0 : stg1, tid, kh, vh, (jt + 1) * 64);
            cp_commit();
            cp_wait<1>();
        } else {
            cp_wait<0>();
        }
        __syncthreads();

        const uint32_t stg = (jt & 1) ? stg1 : stg0;
        const uint32_t skh = stg, svh = stg + 8192;

        const float jb = slope2 * (float)(jt * 64);
        const float b0r = jb + rb0;
        const float b1r = jb + rb1;
        float S[8][4];
        #pragma unroll
        for (int nj = 0; nj < 8; nj++) {
            S[nj][0] = b0r + cnj0[nj];
            S[nj][1] = b0r + cnj1[nj];
            S[nj][2] = b1r + cnj0[nj];
            S[nj][3] = b1r + cnj1[nj];
        }

        #pragma unroll
        for (int kk = 0; kk < 4; kk++) {
            #pragma unroll
            for (int n16 = 0; n16 < 4; n16++) {
                const int r = n16 * 16 + lr;
                uint32_t h0, h1, h2, h3;
                ldsm4(h0, h1, h2, h3, skh + swz128(r, kk*2 + lc));
                mma16816(S[n16*2],   qf[kk], h0, h2);
                mma16816(S[n16*2+1], qf[kk], h1, h3);
            }
        }

        #pragma unroll
        for (int nj = 0; nj < 8; nj++) {
            S[nj][0] = exp2f(S[nj][0]);
            S[nj][1] = exp2f(S[nj][1]);
            S[nj][2] = exp2f(S[nj][2]);
            S[nj][3] = exp2f(S[nj][3]);
        }
        if (jt == njt - 1) {
            const int jbase = jt * 64;
            #pragma unroll
            for (int nj = 0; nj < 8; nj++) {
                const int j0c = jbase + nj * 8 + qc;
                if (j0c > irow0)     S[nj][0] = 0.f;
                if (j0c + 1 > irow0) S[nj][1] = 0.f;
                if (j0c > irow1)     S[nj][2] = 0.f;
                if (j0c + 1 > irow1) S[nj][3] = 0.f;
            }
        }
        #pragma unroll
        for (int nj = 0; nj < 8; nj++) {
            l0 += S[nj][0] + S[nj][1];
            l1 += S[nj][2] + S[nj][3];
        }

        #pragma unroll
        for (int kk = 0; kk < 4; kk++) {
            uint32_t ph[4];
            {
                const float* sA = S[2*kk];
                const float* sB = S[2*kk + 1];
                __half2 t;
                t = __floats2half2_rn(sA[0], sA[1]); ph[0] = *(uint32_t*)&t;
                t = __floats2half2_rn(sA[2], sA[3]); ph[1] = *(uint32_t*)&t;
                t = __floats2half2_rn(sB[0], sB[1]); ph[2] = *(uint32_t*)&t;
                t = __floats2half2_rn(sB[2], sB[3]); ph[3] = *(uint32_t*)&t;
            }
            #pragma unroll
            for (int n16 = 0; n16 < 4; n16++) {
                const int r = kk * 16 + lr;
                uint32_t v0, v1, v2, v3;
                ldsm4t(v0, v1, v2, v3, svh + swz128(r, n16*2 + lc));
                mma16816(O[n16*2],   ph, v0, v1);
                mma16816(O[n16*2+1], ph, v2, v3);
            }
        }
        __syncthreads();
    }

    l0 += __shfl_xor_sync(0xFFFFFFFFu, l0, 1);
    l0 += __shfl_xor_sync(0xFFFFFFFFu, l0, 2);
    l1 += __shfl_xor_sync(0xFFFFFFFFu, l1, 1);
    l1 += __shfl_xor_sync(0xFFFFFFFFu, l1, 2);
    const float inv0 = 1.0f / l0;
    const float inv1 = 1.0f / l1;

    #pragma unroll
    for (int nj = 0; nj < 8; nj++) {
        const int col = h * 64 + nj * 8 + qc;
        const size_t idx0 = (size_t)(b * CT + irow0) * CD + col;
        const size_t idx1 = (size_t)(b * CT + irow1) * CD + col;
        *(__half2*)(oh + idx0) = __floats2half2_rn(O[nj][0] * inv0, O[nj][1] * inv0);
        *(__half2*)(oh + idx1) = __floats2half2_rn(O[nj][2] * inv1, O[nj][3] * inv1);
    }
}

// ---------------------------------------------------------------------------
extern "C" void kernel_launch(void* const* d_in, const int* in_sizes, int n_in,
                              void* d_out, int out_size)
{
    (void)in_sizes; (void)n_in; (void)out_size;
    const float* x  = (const float*)d_in[0];
    const float* Wq = (const float*)d_in[1];
    const float* bq = (const float*)d_in[2];
    const float* Wk = (const float*)d_in[3];
    const float* bk = (const float*)d_in[4];
    const float* Wv = (const float*)d_in[5];
    const float* bv = (const float*)d_in[6];
    const float* Wp = (const float*)d_in[7];
    const float* bp = (const float*)d_in[8];

    __half *ah, *wh, *qh, *kh, *vh;
    cudaGetSymbolAddress((void**)&ah, g_ah);
    cudaGetSymbolAddress((void**)&wh, g_wh);
    cudaGetSymbolAddress((void**)&qh, g_qh);
    cudaGetSymbolAddress((void**)&kh, g_kh);
    cudaGetSymbolAddress((void**)&vh, g_vh);

    cudaFuncSetAttribute(tc_gemm,  cudaFuncAttributeMaxDynamicSharedMemorySize, GSMEM);
    cudaFuncSetAttribute(attn_mma, cudaFuncAttributeMaxDynamicSharedMemorySize, ASMEM);

    const int WN = CD * CD;
    const float invs = 0.17677669529663687f;   // 1024^(-0.25)

    cvt_all<<<(X_N4 + 4*W_N4 + 255)/256, 256>>>(x, Wq, Wk, Wv, Wp, ah, wh);

    tc_gemm<<<dim3(3*CD / GBN, CM / GBM), 256, GSMEM>>>(
        ah, wh, bq, bk, bv, nullptr, qh, kh, vh, invs, 1);

    attn_mma<<<dim3(2*CNH, CT/64), 128, ASMEM>>>(qh, kh, vh, ah);

    tc_gemm<<<dim3(CD / GBN, CM / GBM), 256, GSMEM>>>(
        ah, wh + 3*WN, bp, nullptr, nullptr, (float*)d_out,
        nullptr, nullptr, nullptr, 1.0f, 0);
}

// round 14
// speedup vs baseline: 3.0221x; 1.0079x over previous
#include <cuda_runtime.h>
#include <cuda_fp16.h>
#include <cstdint>

// Problem constants
#define CB 2
#define CT 2048
#define CD 1024
#define CNH 16
#define CHD 64
#define CM (CB*CT)              // 4096 rows

#define LOG2E 1.4426950408889634f

// ---------------------------------------------------------------------------
// Scratch (device globals)
// ---------------------------------------------------------------------------
__device__ __half g_ah[CM*CD];          // A operand (x, then att out)
__device__ __half g_wh[4*CD*CD];        // Wq|Wk|Wv|Wp stacked, fp16
__device__ __half g_qh[CM*CD];          // head-major [B,NH,T,64]; Q pre-scaled by log2e
__device__ __half g_kh[CM*CD];
__device__ __half g_vh[CM*CD];

// ---------------------------------------------------------------------------
// PTX helpers
// ---------------------------------------------------------------------------
static __device__ __forceinline__ void cp16(uint32_t d, const void* s) {
    asm volatile("cp.async.cg.shared.global [%0], [%1], 16;\n" :: "r"(d), "l"(s));
}
static __device__ __forceinline__ void cp_commit() {
    asm volatile("cp.async.commit_group;\n" ::: "memory");
}
template<int N> static __device__ __forceinline__ void cp_wait() {
    asm volatile("cp.async.wait_group %0;\n" :: "n"(N) : "memory");
}
static __device__ __forceinline__ void ldsm4(uint32_t& r0, uint32_t& r1,
                                             uint32_t& r2, uint32_t& r3, uint32_t a) {
    asm volatile("ldmatrix.sync.aligned.m8n8.x4.shared.b16 {%0,%1,%2,%3}, [%4];"
                 : "=r"(r0), "=r"(r1), "=r"(r2), "=r"(r3) : "r"(a));
}
static __device__ __forceinline__ void ldsm4t(uint32_t& r0, uint32_t& r1,
                                              uint32_t& r2, uint32_t& r3, uint32_t a) {
    asm volatile("ldmatrix.sync.aligned.m8n8.x4.trans.shared.b16 {%0,%1,%2,%3}, [%4];"
                 : "=r"(r0), "=r"(r1), "=r"(r2), "=r"(r3) : "r"(a));
}
static __device__ __forceinline__ void mma16816(float* c, const uint32_t* a,
                                                uint32_t b0, uint32_t b1) {
    asm volatile(
        "mma.sync.aligned.m16n8k16.row.col.f32.f16.f16.f32 "
        "{%0,%1,%2,%3}, {%4,%5,%6,%7}, {%8,%9}, {%0,%1,%2,%3};"
        : "+f"(c[0]), "+f"(c[1]), "+f"(c[2]), "+f"(c[3])
        : "r"(a[0]), "r"(a[1]), "r"(a[2]), "r"(a[3]), "r"(b0), "r"(b1));
}
static __device__ __forceinline__ uint32_t smem_u32(const void* p) {
    uint32_t r;
    asm("{ .reg .u64 t; cvta.to.shared.u64 t, %1; cvt.u32.u64 %0, t; }" : "=r"(r) : "l"(p));
    return r;
}

// 128B-row swizzle (shared by GEMM and attention tiles)
static __device__ __forceinline__ uint32_t swz128(int r, int c16) {
    return (uint32_t)(r * 128 + ((c16 ^ (r & 7)) << 4));
}

// ---------------------------------------------------------------------------
// Fused fp32 -> fp16 conversion: x (1M float4) + 4 weights (1M float4), 1 launch
// ---------------------------------------------------------------------------
#define X_N4 (CM*CD/4)                 // 1048576
#define W_N4 (CD*CD/4)                 // 262144
__global__ __launch_bounds__(256)
void cvt_all(const float* __restrict__ x,
             const float* __restrict__ w0, const float* __restrict__ w1,
             const float* __restrict__ w2, const float* __restrict__ w3,
             __half* __restrict__ dx, __half* __restrict__ dw)
{
    int i = blockIdx.x * blockDim.x + threadIdx.x;
    if (i >= X_N4 + 4 * W_N4) return;
    const float* s;
    __half* d;
    int j;
    if (i < X_N4) {
        s = x; d = dx; j = i;
    } else {
        const int k = i - X_N4;
        const int p = k >> 18;
        j = k & (W_N4 - 1);
        s = (p == 0) ? w0 : (p == 1) ? w1 : (p == 2) ? w2 : w3;
        d = dw + (size_t)p * (CD*CD);
    }
    float4 v = ((const float4*)s)[j];
    ((__half2*)d)[2*j]   = __floats2half2_rn(v.x, v.y);
    ((__half2*)d)[2*j+1] = __floats2half2_rn(v.z, v.w);
}

// ---------------------------------------------------------------------------
// mma.sync fp16 GEMM: C = A @ B^T.  (unchanged from R13)
// Stage = BK 64: A 16KB | B 16KB = 32KB; 3 stages = 96KB, 2 CTAs/SM.
// mode 0: out = C+bias0 fp32 row-major [CM,CD]
// mode 1: fused QKV (N=3072): p=bn>>10 -> {q,k,v}; q scaled by invs*log2e.
// ---------------------------------------------------------------------------
#define GBM 128
#define GBN 128
#define GBK 64
#define GSTAGES 3
#define GNKT (CD/GBK)                  // 16
#define PARTB 16384
#define STG_BYTES (2*PARTB)            // 32KB
#define GSMEM (GSTAGES*STG_BYTES)      // 96KB

static __device__ __forceinline__ void g_load_stage(
    uint32_t sbase, int kt, int tid,
    const __half* __restrict__ Ah, const __half* __restrict__ Bh,
    int bm, int bn)
{
    const int k0 = kt * GBK;
    #pragma unroll
    for (int i = 0; i < 8; i++) {
        const int id = tid + i * 256;          // 0..2047
        const int p = id >> 10;                // 0 = A, 1 = B
        const int inner = id & 1023;
        const int r = inner >> 3;
        const int c = inner & 7;
        const int rowbase = p ? bn : bm;
        cp16(sbase + (uint32_t)p * PARTB + swz128(r, c),
             (p ? Bh : Ah) + (size_t)(rowbase + r) * CD + k0 + c * 8);
    }
}

__global__ __launch_bounds__(256, 2)
void tc_gemm(const __half* __restrict__ Ah, const __half* __restrict__ Bh,
             const float* __restrict__ bias0, const float* __restrict__ bias1,
             const float* __restrict__ bias2,
             float* __restrict__ dstf,
             __half* __restrict__ dq, __half* __restrict__ dk,
             __half* __restrict__ dv,
             float invs, int mode)
{
    extern __shared__ char dsm[];
    uint32_t sb = smem_u32(dsm);

    const int tid  = threadIdx.x;
    const int wid  = tid >> 5;
    const int lane = tid & 31;
    const int bm   = blockIdx.y * GBM;
    const int bn   = blockIdx.x * GBN;
    const int m0w  = (wid & 3) * 32;
    const int n0w  = (wid >> 2) * 64;

    float acc[2][8][4];
    #pragma unroll
    for (int i = 0; i < 2; i++)
        #pragma unroll
        for (int j = 0; j < 8; j++)
            #pragma unroll
            for (int k = 0; k < 4; k++) acc[i][j][k] = 0.f;

    #pragma unroll
    for (int s = 0; s < GSTAGES - 1; s++) {
        g_load_stage(sb + s * STG_BYTES, s, tid, Ah, Bh, bm, bn);
        cp_commit();
    }

    const int lr = lane & 15;
    const int lc = lane >> 4;

    for (int kt = 0; kt < GNKT; kt++) {
        cp_wait<GSTAGES - 2>();
        __syncthreads();

        if (kt + GSTAGES - 1 < GNKT) {
            g_load_stage(sb + ((kt + GSTAGES - 1) % GSTAGES) * STG_BYTES,
                         kt + GSTAGES - 1, tid, Ah, Bh, bm, bn);
        }
        cp_commit();

        const uint32_t stg = sb + (uint32_t)(kt % GSTAGES) * STG_BYTES;
        #pragma unroll
        for (int ks = 0; ks < 4; ks++) {
            const int c16 = 2 * ks + lc;
            uint32_t a0[2][4];
            #pragma unroll
            for (int mi = 0; mi < 2; mi++) {
                const int r = m0w + mi * 16 + lr;
                ldsm4(a0[mi][0], a0[mi][1], a0[mi][2], a0[mi][3],
                      stg + swz128(r, c16));
            }
            #pragma unroll
            for (int bj = 0; bj < 4; bj++) {
                const int r = n0w + bj * 16 + lr;
                uint32_t h0, h1, h2, h3;
                ldsm4(h0, h1, h2, h3, stg + PARTB + swz128(r, c16));
                #pragma unroll
                for (int mi = 0; mi < 2; mi++) {
                    mma16816(acc[mi][bj*2],   a0[mi], h0, h2);
                    mma16816(acc[mi][bj*2+1], a0[mi], h1, h3);
                }
            }
        }
    }

    const int qr = lane >> 2;
    const int qc = (lane & 3) * 2;

    if (mode == 0) {
        #pragma unroll
        for (int mi = 0; mi < 2; mi++) {
            #pragma unroll
            for (int nj = 0; nj < 8; nj++) {
                const int col = bn + n0w + nj * 8 + qc;
                const float b0 = __ldg(bias0 + col);
                const float b1 = __ldg(bias0 + col + 1);
                const int row0 = bm + m0w + mi * 16 + qr;
                *(float2*)(dstf + (size_t)row0 * CD + col) =
                    make_float2(acc[mi][nj][0] + b0, acc[mi][nj][1] + b1);
                *(float2*)(dstf + (size_t)(row0 + 8) * CD + col) =
                    make_float2(acc[mi][nj][2] + b0, acc[mi][nj][3] + b1);
            }
        }
    } else {
        const int p = bn >> 10;
        __half* dsth = (p == 0) ? dq : (p == 1) ? dk : dv;
        const float* bias = (p == 0) ? bias0 : (p == 1) ? bias1 : bias2;
        const float scl = (p == 0) ? invs * LOG2E : (p == 1) ? invs : 1.0f;
        const int lb = bn & 1023;
        #pragma unroll
        for (int mi = 0; mi < 2; mi++) {
            #pragma unroll
            for (int nj = 0; nj < 8; nj++) {
                const int local = lb + n0w + nj * 8 + qc;
                const float b0 = __ldg(bias + local);
                const float b1 = __ldg(bias + local + 1);
                const int row0 = bm + m0w + mi * 16 + qr;
                const int h = local >> 6;
                const int d = local & 63;
                float v00 = (acc[mi][nj][0] + b0) * scl;
                float v01 = (acc[mi][nj][1] + b1) * scl;
                float v10 = (acc[mi][nj][2] + b0) * scl;
                float v11 = (acc[mi][nj][3] + b1) * scl;
                #pragma unroll
                for (int rr = 0; rr < 2; rr++) {
                    const int row = row0 + rr * 8;
                    const float x0 = rr ? v10 : v00;
                    const float x1 = rr ? v11 : v01;
                    const int bb = row >> 11;
                    const int t  = row & (CT - 1);
                    const size_t idx = ((size_t)((bb * CNH + h) * CT + t)) * 64 + d;
                    *(__half2*)(dsth + idx) = __floats2half2_rn(x0, x1);
                }
            }
        }
    }
}

// ---------------------------------------------------------------------------
// fp16 flash attention, ALiBi + causal, static-max log2-domain softmax.
// NEW: 3-stage KV ring, prefetch distance 2, ONE __syncthreads per key tile.
// smem: Q 8K | 3 x (K 8K | V 8K) = 56KB -> 3 CTAs/SM (reg-limited).
// ---------------------------------------------------------------------------
#define A_QBYTES 8192
#define A_STG    16384
#define A_NSTG   3
#define ASMEM    (A_QBYTES + A_NSTG*A_STG)   // 56KB

static __device__ __forceinline__ void a_load_kv(
    uint32_t stg, int tid,
    const __half* __restrict__ kh, const __half* __restrict__ vh, int j0)
{
    #pragma unroll
    for (int i = 0; i < 8; i++) {
        const int id = tid + i * 128;
        const int p = id >> 9;               // 0 = K, 1 = V
        const int inner = id & 511;
        const int r = inner >> 3, c = inner & 7;
        cp16(stg + (uint32_t)p * 8192 + swz128(r, c),
             (p ? vh : kh) + (size_t)(j0 + r) * 64 + c * 8);
    }
}

__global__ __launch_bounds__(128, 3)
void attn_mma(const __half* __restrict__ qh_, const __half* __restrict__ kh_,
              const __half* __restrict__ vh_, __half* __restrict__ oh)
{
    extern __shared__ char dsm[];
    const uint32_t sb = smem_u32(dsm);
    const uint32_t sqh = sb;
    const uint32_t stgb = sb + A_QBYTES;

    const int tid  = threadIdx.x;
    const int lane = tid & 31;
    const int w    = tid >> 5;
    const int hb   = blockIdx.x;               // 0..31
    const int h    = hb >> 1;
    const int b    = hb & 1;
    const int tq   = 31 - (int)blockIdx.y;     // longest first
    const int i0   = tq * 64;
    const int njt  = tq + 1;

    const size_t base = (size_t)(b * CNH + h) * CT * 64;
    const __half* qh = qh_ + base;
    const __half* kh = kh_ + base;
    const __half* vh = vh_ + base;

    const float slope2 = exp2f(-0.5f * (float)(h + 1)) * LOG2E;

    // Prologue: group0 = Q + kv tile 0; group1 = kv tile 1 (always in-bounds:
    // tile index 1 < 32 -> rows 64..127 of this head's 2048-row region).
    #pragma unroll
    for (int i = 0; i < 4; i++) {
        const int id = tid + i * 128;
        const int r = id >> 3, c = id & 7;
        cp16(sqh + swz128(r, c), qh + (size_t)(i0 + r) * 64 + c * 8);
    }
    a_load_kv(stgb, tid, kh, vh, 0);
    cp_commit();
    a_load_kv(stgb + A_STG, tid, kh, vh, 64);
    cp_commit();

    cp_wait<1>();            // Q + kv0 ready
    __syncthreads();

    const int lr = lane & 15;
    const int lc = lane >> 4;
    uint32_t qf[4][4];
    #pragma unroll
    for (int kk = 0; kk < 4; kk++) {
        const int r = w * 16 + lr;
        ldsm4(qf[kk][0], qf[kk][1], qf[kk][2], qf[kk][3], sqh + swz128(r, kk*2 + lc));
    }

    const int qr = lane >> 2;
    const int qc = (lane & 3) * 2;
    const int irow0 = i0 + w * 16 + qr;
    const int irow1 = irow0 + 8;

    float cnj0[8], cnj1[8];
    #pragma unroll
    for (int nj = 0; nj < 8; nj++) {
        cnj0[nj] = slope2 * (float)(nj * 8 + qc);
        cnj1[nj] = cnj0[nj] + slope2;
    }
    const float rb0 = -slope2 * (float)irow0 - LOG2E;
    const float rb1 = -slope2 * (float)irow1 - LOG2E;

    float O[8][4];
    #pragma unroll
    for (int nj = 0; nj < 8; nj++)
        #pragma unroll
        for (int e = 0; e < 4; e++) O[nj][e] = 0.f;
    float l0 = 0.f, l1 = 0.f;

    for (int jt = 0; jt < njt; jt++) {
        if (jt > 0) {
            if (jt == njt - 1) cp_wait<0>(); else cp_wait<1>();
            __syncthreads();     // all warps done with tile jt-1 -> safe to
                                 // overwrite buffer (jt+2)%3 == (jt-1)%3
        }
        if (jt + 2 < njt) {
            a_load_kv(stgb + (uint32_t)((jt + 2) % A_NSTG) * A_STG,
                      tid, kh, vh, (jt + 2) * 64);
            cp_commit();
        }

        const uint32_t stg = stgb + (uint32_t)(jt % A_NSTG) * A_STG;
        const uint32_t skh = stg, svh = stg + 8192;

        const float jb = slope2 * (float)(jt * 64);
        const float b0r = jb + rb0;
        const float b1r = jb + rb1;
        float S[8][4];
        #pragma unroll
        for (int nj = 0; nj < 8; nj++) {
            S[nj][0] = b0r + cnj0[nj];
            S[nj][1] = b0r + cnj1[nj];
            S[nj][2] = b1r + cnj0[nj];
            S[nj][3] = b1r + cnj1[nj];
        }

        #pragma unroll
        for (int kk = 0; kk < 4; kk++) {
            #pragma unroll
            for (int n16 = 0; n16 < 4; n16++) {
                const int r = n16 * 16 + lr;
                uint32_t h0, h1, h2, h3;
                ldsm4(h0, h1, h2, h3, skh + swz128(r, kk*2 + lc));
                mma16816(S[n16*2],   qf[kk], h0, h2);
                mma16816(S[n16*2+1], qf[kk], h1, h3);
            }
        }

        #pragma unroll
        for (int nj = 0; nj < 8; nj++) {
            S[nj][0] = exp2f(S[nj][0]);
            S[nj][1] = exp2f(S[nj][1]);
            S[nj][2] = exp2f(S[nj][2]);
            S[nj][3] = exp2f(S[nj][3]);
        }
        if (jt == njt - 1) {
            const int jbase = jt * 64;
            #pragma unroll
            for (int nj = 0; nj < 8; nj++) {
                const int j0c = jbase + nj * 8 + qc;
                if (j0c > irow0)     S[nj][0] = 0.f;
                if (j0c + 1 > irow0) S[nj][1] = 0.f;
                if (j0c > irow1)     S[nj][2] = 0.f;
                if (j0c + 1 > irow1) S[nj][3] = 0.f;
            }
        }
        #pragma unroll
        for (int nj = 0; nj < 8; nj++) {
            l0 += S[nj][0] + S[nj][1];
            l1 += S[nj][2] + S[nj][3];
        }

        #pragma unroll
        for (int kk = 0; kk < 4; kk++) {
            uint32_t ph[4];
            {
                const float* sA = S[2*kk];
                const float* sB = S[2*kk + 1];
                __half2 t;
                t = __floats2half2_rn(sA[0], sA[1]); ph[0] = *(uint32_t*)&t;
                t = __floats2half2_rn(sA[2], sA[3]); ph[1] = *(uint32_t*)&t;
                t = __floats2half2_rn(sB[0], sB[1]); ph[2] = *(uint32_t*)&t;
                t = __floats2half2_rn(sB[2], sB[3]); ph[3] = *(uint32_t*)&t;
            }
            #pragma unroll
            for (int n16 = 0; n16 < 4; n16++) {
                const int r = kk * 16 + lr;
                uint32_t v0, v1, v2, v3;
                ldsm4t(v0, v1, v2, v3, svh + swz128(r, n16*2 + lc));
                mma16816(O[n16*2],   ph, v0, v1);
                mma16816(O[n16*2+1], ph, v2, v3);
            }
        }
    }

    cp_wait<0>();   // drain any unused in-flight prologue group (njt<=2 cases)

    l0 += __shfl_xor_sync(0xFFFFFFFFu, l0, 1);
    l0 += __shfl_xor_sync(0xFFFFFFFFu, l0, 2);
    l1 += __shfl_xor_sync(0xFFFFFFFFu, l1, 1);
    l1 += __shfl_xor_sync(0xFFFFFFFFu, l1, 2);
    const float inv0 = 1.0f / l0;
    const float inv1 = 1.0f / l1;

    #pragma unroll
    for (int nj = 0; nj < 8; nj++) {
        const int col = h * 64 + nj * 8 + qc;
        const size_t idx0 = (size_t)(b * CT + irow0) * CD + col;
        const size_t idx1 = (size_t)(b * CT + irow1) * CD + col;
        *(__half2*)(oh + idx0) = __floats2half2_rn(O[nj][0] * inv0, O[nj][1] * inv0);
        *(__half2*)(oh + idx1) = __floats2half2_rn(O[nj][2] * inv1, O[nj][3] * inv1);
    }
}

// ---------------------------------------------------------------------------
extern "C" void kernel_launch(void* const* d_in, const int* in_sizes, int n_in,
                              void* d_out, int out_size)
{
    (void)in_sizes; (void)n_in; (void)out_size;
    const float* x  = (const float*)d_in[0];
    const float* Wq = (const float*)d_in[1];
    const float* bq = (const float*)d_in[2];
    const float* Wk = (const float*)d_in[3];
    const float* bk = (const float*)d_in[4];
    const float* Wv = (const float*)d_in[5];
    const float* bv = (const float*)d_in[6];
    const float* Wp = (const float*)d_in[7];
    const float* bp = (const float*)d_in[8];

    __half *ah, *wh, *qh, *kh, *vh;
    cudaGetSymbolAddress((void**)&ah, g_ah);
    cudaGetSymbolAddress((void**)&wh, g_wh);
    cudaGetSymbolAddress((void**)&qh, g_qh);
    cudaGetSymbolAddress((void**)&kh, g_kh);
    cudaGetSymbolAddress((void**)&vh, g_vh);

    cudaFuncSetAttribute(tc_gemm,  cudaFuncAttributeMaxDynamicSharedMemorySize, GSMEM);
    cudaFuncSetAttribute(attn_mma, cudaFuncAttributeMaxDynamicSharedMemorySize, ASMEM);

    const int WN = CD * CD;
    const float invs = 0.17677669529663687f;   // 1024^(-0.25)

    cvt_all<<<(X_N4 + 4*W_N4 + 255)/256, 256>>>(x, Wq, Wk, Wv, Wp, ah, wh);

    tc_gemm<<<dim3(3*CD / GBN, CM / GBM), 256, GSMEM>>>(
        ah, wh, bq, bk, bv, nullptr, qh, kh, vh, invs, 1);

    attn_mma<<<dim3(2*CNH, CT/64), 128, ASMEM>>>(qh, kh, vh, ah);

    tc_gemm<<<dim3(CD / GBN, CM / GBM), 256, GSMEM>>>(
        ah, wh + 3*WN, bp, nullptr, nullptr, (float*)d_out,
        nullptr, nullptr, nullptr, 1.0f, 0);
}